// round 1
// baseline (speedup 1.0000x reference)
#include <cuda_runtime.h>
#include <cuda_bf16.h>
#include <math.h>

// Problem constants
#define BATCH 2
#define SEQ   2048
#define MROWS (BATCH*SEQ)       // 4096
#define DMODEL 1024
#define D3    (3*DMODEL)        // 3072
#define INNER (4*DMODEL)        // 4096
#define NHEAD 16
#define HDIM  64

// ---------------- scratch (device globals; no allocations allowed) ----------
__device__ float g_h  [MROWS*DMODEL];   // LN output (reused for LN1 and LN2)
__device__ float g_qkv[MROWS*D3];       // QKV projection
__device__ float g_o  [MROWS*DMODEL];   // attention output
__device__ float g_x1 [MROWS*DMODEL];   // residual after attention
__device__ float g_fc1[MROWS*INNER];    // FC1+GELU output

// ---------------- LayerNorm ----------------
__global__ __launch_bounds__(256) void ln_kernel(
    const float* __restrict__ x, const float* __restrict__ g,
    const float* __restrict__ b, float* __restrict__ out)
{
    __shared__ float red[16];
    const long row = blockIdx.x;
    const float* xr = x + row * DMODEL;
    const int tid = threadIdx.x;

    float v[4];
    float s1 = 0.f, s2 = 0.f;
#pragma unroll
    for (int i = 0; i < 4; i++) {
        v[i] = xr[tid + 256 * i];
        s1 += v[i];
        s2 += v[i] * v[i];
    }
#pragma unroll
    for (int o = 16; o; o >>= 1) {
        s1 += __shfl_xor_sync(0xffffffffu, s1, o);
        s2 += __shfl_xor_sync(0xffffffffu, s2, o);
    }
    if ((tid & 31) == 0) { red[tid >> 5] = s1; red[8 + (tid >> 5)] = s2; }
    __syncthreads();
    if (tid < 32) {
        float a = (tid < 8) ? red[tid] : 0.f;
        float c = (tid < 8) ? red[8 + tid] : 0.f;
#pragma unroll
        for (int o = 4; o; o >>= 1) {
            a += __shfl_xor_sync(0xffffffffu, a, o);
            c += __shfl_xor_sync(0xffffffffu, c, o);
        }
        if (tid == 0) { red[0] = a; red[8] = c; }
    }
    __syncthreads();
    const float mu  = red[0] * (1.f / DMODEL);
    const float var = red[8] * (1.f / DMODEL) - mu * mu;
    const float r   = rsqrtf(var + 1e-5f);
#pragma unroll
    for (int i = 0; i < 4; i++) {
        const int c = tid + 256 * i;
        out[row * DMODEL + c] = (v[i] - mu) * r * g[c] + b[c];
    }
}

// ---------------- SGEMM: C = A(MxK) @ B(KxN) + bias [+res] [gelu] -----------
// EPI: 0 = bias only, 1 = bias + residual, 2 = bias + exact-erf GELU
template<int EPI>
__global__ __launch_bounds__(256) void sgemm_kernel(
    const float* __restrict__ A, const float* __restrict__ B,
    const float* __restrict__ bias, const float* __restrict__ res,
    float* __restrict__ C, int M, int N, int K)
{
    __shared__ float As[8][128];
    __shared__ float Bs[8][128];

    const int tid = threadIdx.x;
    const int tx = tid & 15;        // N direction
    const int ty = tid >> 4;        // M direction
    const int arow = tid >> 1;              // A tile: 128 rows x 8 cols
    const int acol = (tid & 1) * 4;
    const int brow = tid >> 5;              // B tile: 8 rows x 128 cols
    const int bcol = (tid & 31) * 4;

    const float* Ab = A + (long)(blockIdx.y * 128) * K;
    const float* Bb = B + blockIdx.x * 128;

    float acc[8][8];
#pragma unroll
    for (int i = 0; i < 8; i++)
#pragma unroll
        for (int j = 0; j < 8; j++) acc[i][j] = 0.f;

    const int nk = K >> 3;
    float4 a4 = *(const float4*)(Ab + (long)arow * K + acol);
    float4 b4 = *(const float4*)(Bb + (long)brow * N + bcol);

    for (int t = 0; t < nk; t++) {
        As[acol + 0][arow] = a4.x;
        As[acol + 1][arow] = a4.y;
        As[acol + 2][arow] = a4.z;
        As[acol + 3][arow] = a4.w;
        *(float4*)&Bs[brow][bcol] = b4;
        __syncthreads();

        if (t + 1 < nk) {
            const int k0 = (t + 1) * 8;
            a4 = *(const float4*)(Ab + (long)arow * K + k0 + acol);
            b4 = *(const float4*)(Bb + (long)(k0 + brow) * N + bcol);
        }

#pragma unroll
        for (int kk = 0; kk < 8; kk++) {
            float af[8], bf[8];
#pragma unroll
            for (int i = 0; i < 8; i++) af[i] = As[kk][i * 16 + ty];
#pragma unroll
            for (int j = 0; j < 8; j++) bf[j] = Bs[kk][j * 16 + tx];
#pragma unroll
            for (int i = 0; i < 8; i++)
#pragma unroll
                for (int j = 0; j < 8; j++) acc[i][j] += af[i] * bf[j];
        }
        __syncthreads();
    }

#pragma unroll
    for (int i = 0; i < 8; i++) {
        const long row = blockIdx.y * 128 + i * 16 + ty;
#pragma unroll
        for (int j = 0; j < 8; j++) {
            const int col = blockIdx.x * 128 + j * 16 + tx;
            float v = acc[i][j] + bias[col];
            if (EPI == 1) v += res[row * N + col];
            if (EPI == 2) v = 0.5f * v * (1.f + erff(v * 0.70710678118654752f));
            C[row * N + col] = v;
        }
    }
}

// ---------------- Flash-style causal attention (fp32) ------------------
// qkv layout: [B, L, 3*DMODEL], q at col h*64+d, k at 1024+h*64+d, v at 2048+...
// Each block: one (b,h), 64 query rows. Streams key blocks of 64 (kb <= qb).
#define ATT_SMEM ((64 * 65 * 3 + 64 * 64) * 4)

__global__ __launch_bounds__(256) void attn_kernel(
    const float* __restrict__ qkv, float* __restrict__ o)
{
    extern __shared__ float sm[];
    float* Qs = sm;               // [64][65]
    float* Ks = Qs + 64 * 65;     // [64][65]
    float* Ss = Ks + 64 * 65;     // [64][65]
    float* Vs = Ss + 64 * 65;     // [64][64] (exact for float4)

    const int tid = threadIdx.x;
    const int bh = blockIdx.y;
    const int b = bh >> 4;
    const int h = bh & 15;
    const int qb = blockIdx.x;
    const float* base = qkv + (long)b * SEQ * D3 + h * HDIM;

    // load Q tile (64 rows x 64 cols)
    {
        const int r = tid >> 2;
        const float* qrow = base + (long)(qb * 64 + r) * D3;
#pragma unroll
        for (int rep = 0; rep < 4; rep++) {
            const int d4 = ((tid & 3) + rep * 4) * 4;
            float4 q4 = *(const float4*)(qrow + d4);
            Qs[r * 65 + d4 + 0] = q4.x;
            Qs[r * 65 + d4 + 1] = q4.y;
            Qs[r * 65 + d4 + 2] = q4.z;
            Qs[r * 65 + d4 + 3] = q4.w;
        }
    }

    const int tx = tid & 15, ty = tid >> 4;   // score-phase mapping (4x4 tile)
    const int r2 = tid >> 2, cg = tid & 3;    // softmax/PV mapping (row, 16-col group)

    float m = -1e30f, l = 0.f;
    float Oacc[16];
#pragma unroll
    for (int i = 0; i < 16; i++) Oacc[i] = 0.f;

    for (int kb = 0; kb <= qb; kb++) {
        __syncthreads();   // prior iteration's reads of Ks/Vs/Ss done (also covers Q load)
        // load K and V tiles
        {
            const int r = tid >> 2;
            const float* krow = base + (long)(kb * 64 + r) * D3 + DMODEL;
            const float* vrow = krow + DMODEL;
#pragma unroll
            for (int rep = 0; rep < 4; rep++) {
                const int d4 = ((tid & 3) + rep * 4) * 4;
                float4 k4 = *(const float4*)(krow + d4);
                Ks[r * 65 + d4 + 0] = k4.x;
                Ks[r * 65 + d4 + 1] = k4.y;
                Ks[r * 65 + d4 + 2] = k4.z;
                Ks[r * 65 + d4 + 3] = k4.w;
                float4 v4 = *(const float4*)(vrow + d4);
                *(float4*)&Vs[r * 64 + d4] = v4;
            }
        }
        __syncthreads();

        // score phase: each thread computes 4x4 scores
        float sc[4][4];
#pragma unroll
        for (int i = 0; i < 4; i++)
#pragma unroll
            for (int j = 0; j < 4; j++) sc[i][j] = 0.f;

#pragma unroll 4
        for (int d = 0; d < 64; d++) {
            float qv[4], kv[4];
#pragma unroll
            for (int i = 0; i < 4; i++) qv[i] = Qs[(ty * 4 + i) * 65 + d];
#pragma unroll
            for (int j = 0; j < 4; j++) kv[j] = Ks[(tx * 4 + j) * 65 + d];
#pragma unroll
            for (int i = 0; i < 4; i++)
#pragma unroll
                for (int j = 0; j < 4; j++) sc[i][j] += qv[i] * kv[j];
        }

        const bool diag = (kb == qb);
#pragma unroll
        for (int i = 0; i < 4; i++)
#pragma unroll
            for (int j = 0; j < 4; j++) {
                float s = sc[i][j] * 0.125f;          // 1/sqrt(64)
                if (diag && (tx * 4 + j) > (ty * 4 + i)) s = -1e30f;
                Ss[(ty * 4 + i) * 65 + tx * 4 + j] = s;
            }
        __syncthreads();

        // online softmax (threads r2*4+cg are 4 consecutive lanes of one warp)
        float sv[16];
        float mpart = -1e30f;
#pragma unroll
        for (int jj = 0; jj < 16; jj++) {
            sv[jj] = Ss[r2 * 65 + cg * 16 + jj];
            mpart = fmaxf(mpart, sv[jj]);
        }
        mpart = fmaxf(mpart, __shfl_xor_sync(0xffffffffu, mpart, 1));
        mpart = fmaxf(mpart, __shfl_xor_sync(0xffffffffu, mpart, 2));
        const float mnew = fmaxf(m, mpart);
        const float f = __expf(m - mnew);
        float psum = 0.f;
#pragma unroll
        for (int jj = 0; jj < 16; jj++) {
            const float p = __expf(sv[jj] - mnew);
            sv[jj] = p;
            psum += p;
        }
        psum += __shfl_xor_sync(0xffffffffu, psum, 1);
        psum += __shfl_xor_sync(0xffffffffu, psum, 2);
        l = l * f + psum;
        m = mnew;
#pragma unroll
        for (int i = 0; i < 16; i++) Oacc[i] *= f;
        // write probabilities back (read only by same-warp threads)
#pragma unroll
        for (int jj = 0; jj < 16; jj++) Ss[r2 * 65 + cg * 16 + jj] = sv[jj];
        __syncwarp();

        // PV accumulate: O[r2][cg*16 .. +15]
        for (int j = 0; j < 64; j++) {
            const float p = Ss[r2 * 65 + j];
#pragma unroll
            for (int i4 = 0; i4 < 4; i4++) {
                float4 v4 = *(const float4*)&Vs[j * 64 + cg * 16 + i4 * 4];
                Oacc[i4 * 4 + 0] += p * v4.x;
                Oacc[i4 * 4 + 1] += p * v4.y;
                Oacc[i4 * 4 + 2] += p * v4.z;
                Oacc[i4 * 4 + 3] += p * v4.w;
            }
        }
    }

    const float inv = 1.f / l;
    const long obase = ((long)b * SEQ + qb * 64 + r2) * DMODEL + h * HDIM + cg * 16;
#pragma unroll
    for (int i = 0; i < 16; i++) o[obase + i] = Oacc[i] * inv;
}

// ---------------- launcher ----------------
extern "C" void kernel_launch(void* const* d_in, const int* in_sizes, int n_in,
                              void* d_out, int out_size)
{
    const float* x     = (const float*)d_in[0];
    const float* w_qkv = (const float*)d_in[1];
    const float* b_qkv = (const float*)d_in[2];
    const float* w_out = (const float*)d_in[3];
    const float* b_out = (const float*)d_in[4];
    const float* w_fc1 = (const float*)d_in[5];
    const float* b_fc1 = (const float*)d_in[6];
    const float* w_fc2 = (const float*)d_in[7];
    const float* b_fc2 = (const float*)d_in[8];
    const float* ln1_g = (const float*)d_in[9];
    const float* ln1_b = (const float*)d_in[10];
    const float* ln2_g = (const float*)d_in[11];
    const float* ln2_b = (const float*)d_in[12];
    float* out = (float*)d_out;

    float *h, *qkv, *o, *x1, *fc1;
    cudaGetSymbolAddress((void**)&h,   g_h);
    cudaGetSymbolAddress((void**)&qkv, g_qkv);
    cudaGetSymbolAddress((void**)&o,   g_o);
    cudaGetSymbolAddress((void**)&x1,  g_x1);
    cudaGetSymbolAddress((void**)&fc1, g_fc1);

    // 1) LN1
    ln_kernel<<<MROWS, 256>>>(x, ln1_g, ln1_b, h);

    // 2) QKV projection: (4096x1024) @ (1024x3072)
    sgemm_kernel<0><<<dim3(D3 / 128, MROWS / 128), 256>>>(
        h, w_qkv, b_qkv, nullptr, qkv, MROWS, D3, DMODEL);

    // 3) causal attention
    cudaFuncSetAttribute(attn_kernel, cudaFuncAttributeMaxDynamicSharedMemorySize, ATT_SMEM);
    attn_kernel<<<dim3(SEQ / 64, BATCH * NHEAD), 256, ATT_SMEM>>>(qkv, o);

    // 4) out projection + residual: x1 = x + o @ w_out + b_out
    sgemm_kernel<1><<<dim3(DMODEL / 128, MROWS / 128), 256>>>(
        o, w_out, b_out, x, x1, MROWS, DMODEL, DMODEL);

    // 5) LN2
    ln_kernel<<<MROWS, 256>>>(x1, ln2_g, ln2_b, h);

    // 6) FC1 + exact GELU: (4096x1024) @ (1024x4096)
    sgemm_kernel<2><<<dim3(INNER / 128, MROWS / 128), 256>>>(
        h, w_fc1, b_fc1, nullptr, fc1, MROWS, INNER, DMODEL);

    // 7) FC2 + residual -> output: out = x1 + fc1 @ w_fc2 + b_fc2
    sgemm_kernel<1><<<dim3(DMODEL / 128, MROWS / 128), 256>>>(
        fc1, w_fc2, b_fc2, x1, out, MROWS, DMODEL, INNER);
}

// round 3
// speedup vs baseline: 1.8101x; 1.8101x over previous
#include <cuda_runtime.h>
#include <cuda_bf16.h>
#include <math.h>
#include <cstdint>

// Problem constants
#define BATCH 2
#define SEQ   2048
#define MROWS (BATCH*SEQ)       // 4096
#define DMODEL 1024
#define D3    (3*DMODEL)        // 3072
#define INNER (4*DMODEL)        // 4096
#define NHEAD 16
#define HDIM  64

// ---------------- scratch (device globals; no allocations allowed) ----------
__device__ float g_h  [MROWS*DMODEL];
__device__ float g_qkv[MROWS*D3];
__device__ float g_o  [MROWS*DMODEL];
__device__ float g_x1 [MROWS*DMODEL];
__device__ float g_fc1[MROWS*INNER];
__device__ float g_wT [12*1024*1024];   // transposed weights

// ---------------- helpers ----------------
__device__ __forceinline__ uint32_t smem_u32(const void* p) {
    uint32_t a;
    asm("{ .reg .u64 t; cvta.to.shared.u64 t, %1; cvt.u32.u64 %0, t; }" : "=r"(a) : "l"(p));
    return a;
}
__device__ __forceinline__ float tf32r(float x) {
    float y;
    asm("cvt.rna.tf32.f32 %0, %1;" : "=f"(y) : "f"(x));
    return y;
}
#define SW128(x) ((x) ^ (((x) >> 3) & 0x70))
#define CP16(sa, ga) \
    asm volatile("cp.async.cg.shared.global [%0], [%1], 16;" :: "r"(sa), "l"(ga) : "memory")

__device__ __forceinline__ void ldsm4(uint32_t* r, uint32_t a) {
    asm volatile("ldmatrix.sync.aligned.m8n8.x4.shared.b16 {%0,%1,%2,%3}, [%4];"
        : "=r"(r[0]), "=r"(r[1]), "=r"(r[2]), "=r"(r[3]) : "r"(a));
}
__device__ __forceinline__ void mma8(float* d, const uint32_t* a, const uint32_t* b) {
    asm volatile("mma.sync.aligned.m16n8k8.row.col.f32.tf32.tf32.f32 "
        "{%0,%1,%2,%3}, {%4,%5,%6,%7}, {%8,%9}, {%0,%1,%2,%3};"
        : "+f"(d[0]), "+f"(d[1]), "+f"(d[2]), "+f"(d[3])
        : "r"(a[0]), "r"(a[1]), "r"(a[2]), "r"(a[3]), "r"(b[0]), "r"(b[1]));
}

// ---------------- transpose (+ tf32 round): dst[C,R] = tf32(src[R,C]^T) -----
__global__ __launch_bounds__(256) void transpose_kernel(
    const float* __restrict__ src, float* __restrict__ dst, int R, int C)
{
    __shared__ float tile[32][33];
    const int c0 = blockIdx.x * 32, r0 = blockIdx.y * 32;
    const int tx = threadIdx.x & 31, ty = threadIdx.x >> 5;
#pragma unroll
    for (int i = 0; i < 4; i++)
        tile[ty + 8 * i][tx] = src[(size_t)(r0 + ty + 8 * i) * C + c0 + tx];
    __syncthreads();
#pragma unroll
    for (int i = 0; i < 4; i++)
        dst[(size_t)(c0 + ty + 8 * i) * R + r0 + tx] = tf32r(tile[tx][ty + 8 * i]);
}

// ---------------- tensor-core GEMM: C = A[M,K] @ Bt[N,K]^T + bias ----------
// EPI: 0 = bias, 1 = bias + residual, 2 = bias + exact GELU (+tf32 round)
#define GEMM_SMEM 65536   // As[2] + Bs[2], 16KB each

template<int EPI>
__global__ __launch_bounds__(256) void sgemm_tc(
    const float* __restrict__ A, const float* __restrict__ Bt,
    const float* __restrict__ bias, const float* __restrict__ res,
    float* __restrict__ C, int M, int N, int K)
{
    extern __shared__ char smem[];
    const uint32_t sb = smem_u32(smem);
    const uint32_t As[2] = { sb,         sb + 16384 };
    const uint32_t Bs[2] = { sb + 32768, sb + 49152 };

    const int tid = threadIdx.x, lane = tid & 31, wid = tid >> 5;
    const int warp_m = wid >> 2, warp_n = wid & 3;
    const int m0 = blockIdx.y * 128, n0 = blockIdx.x * 128;
    const int mb = warp_m * 64, nb = warp_n * 32;

    // ldmatrix per-lane byte offsets (within tile, before swizzle)
    const int u = lane >> 3, ur = lane & 7;
    uint32_t aoff[4], boff[2];
#pragma unroll
    for (int i = 0; i < 4; i++)
        aoff[i] = (uint32_t)(mb + i * 16 + (u & 1) * 8 + ur) * 128 + (u >> 1) * 16;
#pragma unroll
    for (int p = 0; p < 2; p++)
        boff[p] = (uint32_t)(nb + p * 16 + (u >> 1) * 8 + ur) * 128 + (u & 1) * 16;

    float acc[4][4][4];
#pragma unroll
    for (int i = 0; i < 4; i++)
#pragma unroll
        for (int j = 0; j < 4; j++)
#pragma unroll
            for (int q = 0; q < 4; q++) acc[i][j][q] = 0.f;

    const int nk = K >> 5;

    // prologue: chunk 0 -> buf 0
    {
#pragma unroll
        for (int i = 0; i < 4; i++) {
            const int idx = tid + 256 * i;
            const int r = idx >> 3, c = idx & 7;
            const uint32_t so = SW128((uint32_t)r * 128 + c * 16);
            CP16(As[0] + so, A  + (size_t)(m0 + r) * K + c * 4);
            CP16(Bs[0] + so, Bt + (size_t)(n0 + r) * K + c * 4);
        }
        asm volatile("cp.async.commit_group;" ::: "memory");
    }

    for (int t = 0; t < nk; t++) {
        const int b = t & 1;
        if (t + 1 < nk) {
#pragma unroll
            for (int i = 0; i < 4; i++) {
                const int idx = tid + 256 * i;
                const int r = idx >> 3, c = idx & 7;
                const uint32_t so = SW128((uint32_t)r * 128 + c * 16);
                CP16(As[b ^ 1] + so, A  + (size_t)(m0 + r) * K + (t + 1) * 32 + c * 4);
                CP16(Bs[b ^ 1] + so, Bt + (size_t)(n0 + r) * K + (t + 1) * 32 + c * 4);
            }
            asm volatile("cp.async.commit_group;" ::: "memory");
            asm volatile("cp.async.wait_group 1;" ::: "memory");
        } else {
            asm volatile("cp.async.wait_group 0;" ::: "memory");
        }
        __syncthreads();

#pragma unroll
        for (int s = 0; s < 4; s++) {
            uint32_t af[4][4], bf[4][2];
#pragma unroll
            for (int i = 0; i < 4; i++)
                ldsm4(af[i], As[b] + SW128(aoff[i] + s * 32));
#pragma unroll
            for (int p = 0; p < 2; p++) {
                uint32_t r4[4];
                ldsm4(r4, Bs[b] + SW128(boff[p] + s * 32));
                bf[2 * p][0] = r4[0]; bf[2 * p][1] = r4[1];
                bf[2 * p + 1][0] = r4[2]; bf[2 * p + 1][1] = r4[3];
            }
#pragma unroll
            for (int i = 0; i < 4; i++)
#pragma unroll
                for (int j = 0; j < 4; j++) mma8(acc[i][j], af[i], bf[j]);
        }
        __syncthreads();
    }

    // epilogue
    const int r0 = m0 + mb + (lane >> 2);
    const int c0 = n0 + nb + (lane & 3) * 2;
#pragma unroll
    for (int i = 0; i < 4; i++) {
#pragma unroll
        for (int j = 0; j < 4; j++) {
            const int col = c0 + j * 8;
            const float bx = bias[col], by = bias[col + 1];
#pragma unroll
            for (int hh = 0; hh < 2; hh++) {
                const int row = r0 + i * 16 + hh * 8;
                float vx = acc[i][j][hh * 2 + 0] + bx;
                float vy = acc[i][j][hh * 2 + 1] + by;
                if (EPI == 1) {
                    const float2 rr = *(const float2*)(res + (size_t)row * N + col);
                    vx += rr.x; vy += rr.y;
                }
                if (EPI == 2) {
                    vx = tf32r(0.5f * vx * (1.f + erff(vx * 0.70710678118654752f)));
                    vy = tf32r(0.5f * vy * (1.f + erff(vy * 0.70710678118654752f)));
                }
                float2 v; v.x = vx; v.y = vy;
                *(float2*)(C + (size_t)row * N + col) = v;
            }
        }
    }
}

// ---------------- LayerNorm (tf32-rounded output; feeds GEMMs only) --------
__global__ __launch_bounds__(256) void ln_kernel(
    const float* __restrict__ x, const float* __restrict__ g,
    const float* __restrict__ b, float* __restrict__ out)
{
    __shared__ float red[16];
    const long row = blockIdx.x;
    const float* xr = x + row * DMODEL;
    const int tid = threadIdx.x;

    float v[4];
    float s1 = 0.f, s2 = 0.f;
#pragma unroll
    for (int i = 0; i < 4; i++) {
        v[i] = xr[tid + 256 * i];
        s1 += v[i];
        s2 += v[i] * v[i];
    }
#pragma unroll
    for (int o = 16; o; o >>= 1) {
        s1 += __shfl_xor_sync(0xffffffffu, s1, o);
        s2 += __shfl_xor_sync(0xffffffffu, s2, o);
    }
    if ((tid & 31) == 0) { red[tid >> 5] = s1; red[8 + (tid >> 5)] = s2; }
    __syncthreads();
    if (tid < 32) {
        float a = (tid < 8) ? red[tid] : 0.f;
        float c = (tid < 8) ? red[8 + tid] : 0.f;
#pragma unroll
        for (int o = 4; o; o >>= 1) {
            a += __shfl_xor_sync(0xffffffffu, a, o);
            c += __shfl_xor_sync(0xffffffffu, c, o);
        }
        if (tid == 0) { red[0] = a; red[8] = c; }
    }
    __syncthreads();
    const float mu  = red[0] * (1.f / DMODEL);
    const float var = red[8] * (1.f / DMODEL) - mu * mu;
    const float r   = rsqrtf(var + 1e-5f);
#pragma unroll
    for (int i = 0; i < 4; i++) {
        const int c = tid + 256 * i;
        out[row * DMODEL + c] = tf32r((v[i] - mu) * r * g[c] + b[c]);
    }
}

// ---------------- Flash-style causal attention (fp32) ------------------
#define ATT_SMEM ((64 * 65 * 3 + 64 * 64) * 4)

__global__ __launch_bounds__(256) void attn_kernel(
    const float* __restrict__ qkv, float* __restrict__ o)
{
    extern __shared__ float sm[];
    float* Qs = sm;               // [64][65]
    float* Ks = Qs + 64 * 65;     // [64][65]
    float* Ss = Ks + 64 * 65;     // [64][65]
    float* Vs = Ss + 64 * 65;     // [64][64]

    const int tid = threadIdx.x;
    const int bh = blockIdx.y;
    const int b = bh >> 4;
    const int h = bh & 15;
    const int qb = blockIdx.x;
    const float* base = qkv + (long)b * SEQ * D3 + h * HDIM;

    {
        const int r = tid >> 2;
        const float* qrow = base + (long)(qb * 64 + r) * D3;
#pragma unroll
        for (int rep = 0; rep < 4; rep++) {
            const int d4 = ((tid & 3) + rep * 4) * 4;
            float4 q4 = *(const float4*)(qrow + d4);
            Qs[r * 65 + d4 + 0] = q4.x;
            Qs[r * 65 + d4 + 1] = q4.y;
            Qs[r * 65 + d4 + 2] = q4.z;
            Qs[r * 65 + d4 + 3] = q4.w;
        }
    }

    const int tx = tid & 15, ty = tid >> 4;
    const int r2 = tid >> 2, cg = tid & 3;

    float m = -1e30f, l = 0.f;
    float Oacc[16];
#pragma unroll
    for (int i = 0; i < 16; i++) Oacc[i] = 0.f;

    for (int kb = 0; kb <= qb; kb++) {
        __syncthreads();
        {
            const int r = tid >> 2;
            const float* krow = base + (long)(kb * 64 + r) * D3 + DMODEL;
            const float* vrow = krow + DMODEL;
#pragma unroll
            for (int rep = 0; rep < 4; rep++) {
                const int d4 = ((tid & 3) + rep * 4) * 4;
                float4 k4 = *(const float4*)(krow + d4);
                Ks[r * 65 + d4 + 0] = k4.x;
                Ks[r * 65 + d4 + 1] = k4.y;
                Ks[r * 65 + d4 + 2] = k4.z;
                Ks[r * 65 + d4 + 3] = k4.w;
                float4 v4 = *(const float4*)(vrow + d4);
                *(float4*)&Vs[r * 64 + d4] = v4;
            }
        }
        __syncthreads();

        float sc[4][4];
#pragma unroll
        for (int i = 0; i < 4; i++)
#pragma unroll
            for (int j = 0; j < 4; j++) sc[i][j] = 0.f;

#pragma unroll 4
        for (int d = 0; d < 64; d++) {
            float qv[4], kv[4];
#pragma unroll
            for (int i = 0; i < 4; i++) qv[i] = Qs[(ty * 4 + i) * 65 + d];
#pragma unroll
            for (int j = 0; j < 4; j++) kv[j] = Ks[(tx * 4 + j) * 65 + d];
#pragma unroll
            for (int i = 0; i < 4; i++)
#pragma unroll
                for (int j = 0; j < 4; j++) sc[i][j] += qv[i] * kv[j];
        }

        const bool diag = (kb == qb);
#pragma unroll
        for (int i = 0; i < 4; i++)
#pragma unroll
            for (int j = 0; j < 4; j++) {
                float s = sc[i][j] * 0.125f;
                if (diag && (tx * 4 + j) > (ty * 4 + i)) s = -1e30f;
                Ss[(ty * 4 + i) * 65 + tx * 4 + j] = s;
            }
        __syncthreads();

        float sv[16];
        float mpart = -1e30f;
#pragma unroll
        for (int jj = 0; jj < 16; jj++) {
            sv[jj] = Ss[r2 * 65 + cg * 16 + jj];
            mpart = fmaxf(mpart, sv[jj]);
        }
        mpart = fmaxf(mpart, __shfl_xor_sync(0xffffffffu, mpart, 1));
        mpart = fmaxf(mpart, __shfl_xor_sync(0xffffffffu, mpart, 2));
        const float mnew = fmaxf(m, mpart);
        const float f = __expf(m - mnew);
        float psum = 0.f;
#pragma unroll
        for (int jj = 0; jj < 16; jj++) {
            const float p = __expf(sv[jj] - mnew);
            sv[jj] = p;
            psum += p;
        }
        psum += __shfl_xor_sync(0xffffffffu, psum, 1);
        psum += __shfl_xor_sync(0xffffffffu, psum, 2);
        l = l * f + psum;
        m = mnew;
#pragma unroll
        for (int i = 0; i < 16; i++) Oacc[i] *= f;
#pragma unroll
        for (int jj = 0; jj < 16; jj++) Ss[r2 * 65 + cg * 16 + jj] = sv[jj];
        __syncwarp();

        for (int j = 0; j < 64; j++) {
            const float p = Ss[r2 * 65 + j];
#pragma unroll
            for (int i4 = 0; i4 < 4; i4++) {
                float4 v4 = *(const float4*)&Vs[j * 64 + cg * 16 + i4 * 4];
                Oacc[i4 * 4 + 0] += p * v4.x;
                Oacc[i4 * 4 + 1] += p * v4.y;
                Oacc[i4 * 4 + 2] += p * v4.z;
                Oacc[i4 * 4 + 3] += p * v4.w;
            }
        }
    }

    const float inv = 1.f / l;
    const long obase = ((long)b * SEQ + qb * 64 + r2) * DMODEL + h * HDIM + cg * 16;
#pragma unroll
    for (int i = 0; i < 16; i++) o[obase + i] = tf32r(Oacc[i] * inv);
}

// ---------------- launcher ----------------
extern "C" void kernel_launch(void* const* d_in, const int* in_sizes, int n_in,
                              void* d_out, int out_size)
{
    const float* x     = (const float*)d_in[0];
    const float* w_qkv = (const float*)d_in[1];
    const float* b_qkv = (const float*)d_in[2];
    const float* w_out = (const float*)d_in[3];
    const float* b_out = (const float*)d_in[4];
    const float* w_fc1 = (const float*)d_in[5];
    const float* b_fc1 = (const float*)d_in[6];
    const float* w_fc2 = (const float*)d_in[7];
    const float* b_fc2 = (const float*)d_in[8];
    const float* ln1_g = (const float*)d_in[9];
    const float* ln1_b = (const float*)d_in[10];
    const float* ln2_g = (const float*)d_in[11];
    const float* ln2_b = (const float*)d_in[12];
    float* out = (float*)d_out;

    float *h, *qkv, *o, *x1, *fc1, *wT;
    cudaGetSymbolAddress((void**)&h,   g_h);
    cudaGetSymbolAddress((void**)&qkv, g_qkv);
    cudaGetSymbolAddress((void**)&o,   g_o);
    cudaGetSymbolAddress((void**)&x1,  g_x1);
    cudaGetSymbolAddress((void**)&fc1, g_fc1);
    cudaGetSymbolAddress((void**)&wT,  g_wT);

    float* wqkvT = wT;                       // [3072,1024]
    float* woutT = wqkvT + 3072 * 1024;      // [1024,1024]
    float* wfc1T = woutT + 1024 * 1024;      // [4096,1024]
    float* wfc2T = wfc1T + 4096 * 1024;      // [1024,4096]

    cudaFuncSetAttribute(sgemm_tc<0>, cudaFuncAttributeMaxDynamicSharedMemorySize, GEMM_SMEM);
    cudaFuncSetAttribute(sgemm_tc<1>, cudaFuncAttributeMaxDynamicSharedMemorySize, GEMM_SMEM);
    cudaFuncSetAttribute(sgemm_tc<2>, cudaFuncAttributeMaxDynamicSharedMemorySize, GEMM_SMEM);
    cudaFuncSetAttribute(attn_kernel, cudaFuncAttributeMaxDynamicSharedMemorySize, ATT_SMEM);

    // 0) transpose weights (Bt[n][k] = tf32(W[k][n]))
    transpose_kernel<<<dim3(D3 / 32,    DMODEL / 32), 256>>>(w_qkv, wqkvT, DMODEL, D3);
    transpose_kernel<<<dim3(DMODEL / 32, DMODEL / 32), 256>>>(w_out, woutT, DMODEL, DMODEL);
    transpose_kernel<<<dim3(INNER / 32,  DMODEL / 32), 256>>>(w_fc1, wfc1T, DMODEL, INNER);
    transpose_kernel<<<dim3(DMODEL / 32, INNER / 32), 256>>>(w_fc2, wfc2T, INNER, DMODEL);

    // 1) LN1
    ln_kernel<<<MROWS, 256>>>(x, ln1_g, ln1_b, h);

    // 2) QKV projection
    sgemm_tc<0><<<dim3(D3 / 128, MROWS / 128), 256, GEMM_SMEM>>>(
        h, wqkvT, b_qkv, nullptr, qkv, MROWS, D3, DMODEL);

    // 3) causal attention
    attn_kernel<<<dim3(SEQ / 64, BATCH * NHEAD), 256, ATT_SMEM>>>(qkv, o);

    // 4) out projection + residual
    sgemm_tc<1><<<dim3(DMODEL / 128, MROWS / 128), 256, GEMM_SMEM>>>(
        o, woutT, b_out, x, x1, MROWS, DMODEL, DMODEL);

    // 5) LN2
    ln_kernel<<<MROWS, 256>>>(x1, ln2_g, ln2_b, h);

    // 6) FC1 + exact GELU
    sgemm_tc<2><<<dim3(INNER / 128, MROWS / 128), 256, GEMM_SMEM>>>(
        h, wfc1T, b_fc1, nullptr, fc1, MROWS, INNER, DMODEL);

    // 7) FC2 + residual -> out
    sgemm_tc<1><<<dim3(DMODEL / 128, MROWS / 128), 256, GEMM_SMEM>>>(
        fc1, wfc2T, b_fc2, x1, out, MROWS, DMODEL, INNER);
}

// round 4
// speedup vs baseline: 4.9252x; 2.7210x over previous
#include <cuda_runtime.h>
#include <cuda_bf16.h>
#include <math.h>
#include <cstdint>

// Problem constants
#define BATCH 2
#define SEQ   2048
#define MROWS (BATCH*SEQ)       // 4096
#define DMODEL 1024
#define D3    (3*DMODEL)        // 3072
#define INNER (4*DMODEL)        // 4096
#define NHEAD 16
#define HDIM  64

// ---------------- scratch (device globals; no allocations allowed) ----------
__device__ float g_h  [MROWS*DMODEL];
__device__ float g_qkv[MROWS*D3];
__device__ float g_o  [MROWS*DMODEL];
__device__ float g_x1 [MROWS*DMODEL];
__device__ float g_fc1[MROWS*INNER];
__device__ float g_wT [12*1024*1024];   // transposed weights

// ---------------- helpers ----------------
__device__ __forceinline__ uint32_t smem_u32(const void* p) {
    uint32_t a;
    asm("{ .reg .u64 t; cvta.to.shared.u64 t, %1; cvt.u32.u64 %0, t; }" : "=r"(a) : "l"(p));
    return a;
}
__device__ __forceinline__ float tf32r(float x) {
    float y;
    asm("cvt.rna.tf32.f32 %0, %1;" : "=f"(y) : "f"(x));
    return y;
}
#define SW128(x) ((x) ^ (((x) >> 3) & 0x70))
#define CP16(sa, ga) \
    asm volatile("cp.async.cg.shared.global [%0], [%1], 16;" :: "r"(sa), "l"(ga) : "memory")

__device__ __forceinline__ void ldsm4(uint32_t* r, uint32_t a) {
    asm volatile("ldmatrix.sync.aligned.m8n8.x4.shared.b16 {%0,%1,%2,%3}, [%4];"
        : "=r"(r[0]), "=r"(r[1]), "=r"(r[2]), "=r"(r[3]) : "r"(a));
}
__device__ __forceinline__ void mma8(float* d, const uint32_t* a, const uint32_t* b) {
    asm volatile("mma.sync.aligned.m16n8k8.row.col.f32.tf32.tf32.f32 "
        "{%0,%1,%2,%3}, {%4,%5,%6,%7}, {%8,%9}, {%0,%1,%2,%3};"
        : "+f"(d[0]), "+f"(d[1]), "+f"(d[2]), "+f"(d[3])
        : "r"(a[0]), "r"(a[1]), "r"(a[2]), "r"(a[3]), "r"(b[0]), "r"(b[1]));
}

// ---------------- transpose (+ tf32 round): dst[C,R] = tf32(src[R,C]^T) -----
__global__ __launch_bounds__(256) void transpose_kernel(
    const float* __restrict__ src, float* __restrict__ dst, int R, int C)
{
    __shared__ float tile[32][33];
    const int c0 = blockIdx.x * 32, r0 = blockIdx.y * 32;
    const int tx = threadIdx.x & 31, ty = threadIdx.x >> 5;
#pragma unroll
    for (int i = 0; i < 4; i++)
        tile[ty + 8 * i][tx] = src[(size_t)(r0 + ty + 8 * i) * C + c0 + tx];
    __syncthreads();
#pragma unroll
    for (int i = 0; i < 4; i++)
        dst[(size_t)(c0 + ty + 8 * i) * R + r0 + tx] = tf32r(tile[tx][ty + 8 * i]);
}

// ---------------- tensor-core GEMM: C = A[M,K] @ Bt[N,K]^T + bias ----------
#define GEMM_SMEM 65536

template<int EPI>
__global__ __launch_bounds__(256) void sgemm_tc(
    const float* __restrict__ A, const float* __restrict__ Bt,
    const float* __restrict__ bias, const float* __restrict__ res,
    float* __restrict__ C, int M, int N, int K)
{
    extern __shared__ char smem[];
    const uint32_t sb = smem_u32(smem);
    const uint32_t As[2] = { sb,         sb + 16384 };
    const uint32_t Bs[2] = { sb + 32768, sb + 49152 };

    const int tid = threadIdx.x, lane = tid & 31, wid = tid >> 5;
    const int warp_m = wid >> 2, warp_n = wid & 3;
    const int m0 = blockIdx.y * 128, n0 = blockIdx.x * 128;
    const int mb = warp_m * 64, nb = warp_n * 32;

    const int u = lane >> 3, ur = lane & 7;
    uint32_t aoff[4], boff[2];
#pragma unroll
    for (int i = 0; i < 4; i++)
        aoff[i] = (uint32_t)(mb + i * 16 + (u & 1) * 8 + ur) * 128 + (u >> 1) * 16;
#pragma unroll
    for (int p = 0; p < 2; p++)
        boff[p] = (uint32_t)(nb + p * 16 + (u >> 1) * 8 + ur) * 128 + (u & 1) * 16;

    float acc[4][4][4];
#pragma unroll
    for (int i = 0; i < 4; i++)
#pragma unroll
        for (int j = 0; j < 4; j++)
#pragma unroll
            for (int q = 0; q < 4; q++) acc[i][j][q] = 0.f;

    const int nk = K >> 5;

    {
#pragma unroll
        for (int i = 0; i < 4; i++) {
            const int idx = tid + 256 * i;
            const int r = idx >> 3, c = idx & 7;
            const uint32_t so = SW128((uint32_t)r * 128 + c * 16);
            CP16(As[0] + so, A  + (size_t)(m0 + r) * K + c * 4);
            CP16(Bs[0] + so, Bt + (size_t)(n0 + r) * K + c * 4);
        }
        asm volatile("cp.async.commit_group;" ::: "memory");
    }

    for (int t = 0; t < nk; t++) {
        const int b = t & 1;
        if (t + 1 < nk) {
#pragma unroll
            for (int i = 0; i < 4; i++) {
                const int idx = tid + 256 * i;
                const int r = idx >> 3, c = idx & 7;
                const uint32_t so = SW128((uint32_t)r * 128 + c * 16);
                CP16(As[b ^ 1] + so, A  + (size_t)(m0 + r) * K + (t + 1) * 32 + c * 4);
                CP16(Bs[b ^ 1] + so, Bt + (size_t)(n0 + r) * K + (t + 1) * 32 + c * 4);
            }
            asm volatile("cp.async.commit_group;" ::: "memory");
            asm volatile("cp.async.wait_group 1;" ::: "memory");
        } else {
            asm volatile("cp.async.wait_group 0;" ::: "memory");
        }
        __syncthreads();

#pragma unroll
        for (int s = 0; s < 4; s++) {
            uint32_t af[4][4], bf[4][2];
#pragma unroll
            for (int i = 0; i < 4; i++)
                ldsm4(af[i], As[b] + SW128(aoff[i] + s * 32));
#pragma unroll
            for (int p = 0; p < 2; p++) {
                uint32_t r4[4];
                ldsm4(r4, Bs[b] + SW128(boff[p] + s * 32));
                bf[2 * p][0] = r4[0]; bf[2 * p][1] = r4[1];
                bf[2 * p + 1][0] = r4[2]; bf[2 * p + 1][1] = r4[3];
            }
#pragma unroll
            for (int i = 0; i < 4; i++)
#pragma unroll
                for (int j = 0; j < 4; j++) mma8(acc[i][j], af[i], bf[j]);
        }
        __syncthreads();
    }

    const int r0 = m0 + mb + (lane >> 2);
    const int c0 = n0 + nb + (lane & 3) * 2;
#pragma unroll
    for (int i = 0; i < 4; i++) {
#pragma unroll
        for (int j = 0; j < 4; j++) {
            const int col = c0 + j * 8;
            const float bx = bias[col], by = bias[col + 1];
#pragma unroll
            for (int hh = 0; hh < 2; hh++) {
                const int row = r0 + i * 16 + hh * 8;
                float vx = acc[i][j][hh * 2 + 0] + bx;
                float vy = acc[i][j][hh * 2 + 1] + by;
                if (EPI == 1) {
                    const float2 rr = *(const float2*)(res + (size_t)row * N + col);
                    vx += rr.x; vy += rr.y;
                }
                if (EPI == 2) {
                    vx = tf32r(0.5f * vx * (1.f + erff(vx * 0.70710678118654752f)));
                    vy = tf32r(0.5f * vy * (1.f + erff(vy * 0.70710678118654752f)));
                }
                float2 v; v.x = vx; v.y = vy;
                *(float2*)(C + (size_t)row * N + col) = v;
            }
        }
    }
}

// ---------------- LayerNorm (tf32-rounded output; feeds GEMMs) --------
__global__ __launch_bounds__(256) void ln_kernel(
    const float* __restrict__ x, const float* __restrict__ g,
    const float* __restrict__ b, float* __restrict__ out)
{
    __shared__ float red[16];
    const long row = blockIdx.x;
    const float* xr = x + row * DMODEL;
    const int tid = threadIdx.x;

    float v[4];
    float s1 = 0.f, s2 = 0.f;
#pragma unroll
    for (int i = 0; i < 4; i++) {
        v[i] = xr[tid + 256 * i];
        s1 += v[i];
        s2 += v[i] * v[i];
    }
#pragma unroll
    for (int o = 16; o; o >>= 1) {
        s1 += __shfl_xor_sync(0xffffffffu, s1, o);
        s2 += __shfl_xor_sync(0xffffffffu, s2, o);
    }
    if ((tid & 31) == 0) { red[tid >> 5] = s1; red[8 + (tid >> 5)] = s2; }
    __syncthreads();
    if (tid < 32) {
        float a = (tid < 8) ? red[tid] : 0.f;
        float c = (tid < 8) ? red[8 + tid] : 0.f;
#pragma unroll
        for (int o = 4; o; o >>= 1) {
            a += __shfl_xor_sync(0xffffffffu, a, o);
            c += __shfl_xor_sync(0xffffffffu, c, o);
        }
        if (tid == 0) { red[0] = a; red[8] = c; }
    }
    __syncthreads();
    const float mu  = red[0] * (1.f / DMODEL);
    const float var = red[8] * (1.f / DMODEL) - mu * mu;
    const float r   = rsqrtf(var + 1e-5f);
#pragma unroll
    for (int i = 0; i < 4; i++) {
        const int c = tid + 256 * i;
        out[row * DMODEL + c] = tf32r((v[i] - mu) * r * g[c] + b[c]);
    }
}

// ---------------- tensor-core flash attention (tf32 mma) --------------------
// Per CTA: one (b,h), 128 query rows, 8 warps x 16 rows. K-blocks of 64.
// Smem: Qs[128][68] (reused as Ps), Ks[64][68], Vt[64][68]  (stride 68 floats)
#define AT_STRIDE 68
#define ATT_SMEM ((128 + 64 + 64) * AT_STRIDE * 4)   // 69632

__global__ __launch_bounds__(256) void attn_tc_kernel(
    const float* __restrict__ qkv, float* __restrict__ o)
{
    extern __shared__ float sm[];
    float* Qs = sm;                                  // [128][68], reused as Ps
    float* Ks = Qs + 128 * AT_STRIDE;                // [64][68]
    float* Vt = Ks + 64 * AT_STRIDE;                 // [64][68] (hd-major)
    const uint32_t uQs = smem_u32(Qs), uKs = smem_u32(Ks), uVt = smem_u32(Vt);

    const int tid = threadIdx.x, lane = tid & 31, w = tid >> 5;
    const int bh = blockIdx.y;
    const int b = bh >> 4, h = bh & 15;
    const int qb = (int)gridDim.x - 1 - (int)blockIdx.x;   // heavy tiles first
    const int q0 = qb * 128;
    const size_t bL = (size_t)b * SEQ;

    // ldmatrix per-lane byte offsets (row stride 272B; conflict-free, no swizzle)
    const int u = lane >> 3, ur = lane & 7;
    const uint32_t aoff = (uint32_t)(w * 16 + (u & 1) * 8 + ur) * (AT_STRIDE * 4) + (u >> 1) * 16;
    uint32_t boff[4];
#pragma unroll
    for (int p = 0; p < 4; p++)
        boff[p] = (uint32_t)(p * 16 + (u >> 1) * 8 + ur) * (AT_STRIDE * 4) + (u & 1) * 16;

    // ---- load Q tile (tf32-rounded) ----
#pragma unroll
    for (int i = 0; i < 8; i++) {
        const int idx = tid + 256 * i;
        const int r = idx >> 4, c = idx & 15;
        const float4 q4 = *(const float4*)(qkv + (bL + q0 + r) * D3 + h * HDIM + c * 4);
        float* dst = Qs + r * AT_STRIDE + c * 4;
        dst[0] = tf32r(q4.x); dst[1] = tf32r(q4.y);
        dst[2] = tf32r(q4.z); dst[3] = tf32r(q4.w);
    }
    __syncthreads();

    // ---- Q fragments to registers (8 k-steps x 4 regs) ----
    uint32_t qf[8][4];
#pragma unroll
    for (int s = 0; s < 8; s++) ldsm4(qf[s], uQs + aoff + s * 32);

    float oa[8][4];
#pragma unroll
    for (int n = 0; n < 8; n++)
#pragma unroll
        for (int q = 0; q < 4; q++) oa[n][q] = 0.f;
    float m_lo = -1e30f, m_hi = -1e30f, l_lo = 0.f, l_hi = 0.f;

    const int grow_lo = q0 + w * 16 + (lane >> 2);
    const int grow_hi = grow_lo + 8;
    const int nkb = 2 * qb + 2;

    for (int kb = 0; kb < nkb; kb++) {
        __syncthreads();
        // ---- load K tile + transposed V tile ----
#pragma unroll
        for (int i = 0; i < 4; i++) {
            const int idx = tid + 256 * i;
            const int r = idx >> 4, c = idx & 15;
            const float* kp = qkv + (bL + kb * 64 + r) * D3 + DMODEL + h * HDIM + c * 4;
            const float4 k4 = *(const float4*)kp;
            float* kd = Ks + r * AT_STRIDE + c * 4;
            kd[0] = tf32r(k4.x); kd[1] = tf32r(k4.y);
            kd[2] = tf32r(k4.z); kd[3] = tf32r(k4.w);
            const float4 v4 = *(const float4*)(kp + DMODEL);
            Vt[(c * 4 + 0) * AT_STRIDE + r] = tf32r(v4.x);
            Vt[(c * 4 + 1) * AT_STRIDE + r] = tf32r(v4.y);
            Vt[(c * 4 + 2) * AT_STRIDE + r] = tf32r(v4.z);
            Vt[(c * 4 + 3) * AT_STRIDE + r] = tf32r(v4.w);
        }
        __syncthreads();

        // ---- S = Q @ K^T ----
        float sc[8][4];
#pragma unroll
        for (int n = 0; n < 8; n++)
#pragma unroll
            for (int q = 0; q < 4; q++) sc[n][q] = 0.f;
#pragma unroll
        for (int s = 0; s < 8; s++) {
            uint32_t bf[8][2];
#pragma unroll
            for (int p = 0; p < 4; p++) {
                uint32_t r4[4];
                ldsm4(r4, uKs + boff[p] + s * 32);
                bf[2 * p][0] = r4[0]; bf[2 * p][1] = r4[1];
                bf[2 * p + 1][0] = r4[2]; bf[2 * p + 1][1] = r4[3];
            }
#pragma unroll
            for (int n = 0; n < 8; n++) mma8(sc[n], qf[s], bf[n]);
        }

        // ---- scale + causal mask ----
        const bool need_mask = (kb >= 2 * qb);
        const int c0g = kb * 64 + (lane & 3) * 2;
#pragma unroll
        for (int n = 0; n < 8; n++) {
            const int col0 = c0g + n * 8, col1 = col0 + 1;
            float s0 = sc[n][0] * 0.125f, s1 = sc[n][1] * 0.125f;
            float s2 = sc[n][2] * 0.125f, s3 = sc[n][3] * 0.125f;
            if (need_mask) {
                if (col0 > grow_lo) s0 = -1e30f;
                if (col1 > grow_lo) s1 = -1e30f;
                if (col0 > grow_hi) s2 = -1e30f;
                if (col1 > grow_hi) s3 = -1e30f;
            }
            sc[n][0] = s0; sc[n][1] = s1; sc[n][2] = s2; sc[n][3] = s3;
        }

        // ---- online softmax (rows split across 4 lanes: lane&~3 group) ----
        float bm_lo = -1e30f, bm_hi = -1e30f;
#pragma unroll
        for (int n = 0; n < 8; n++) {
            bm_lo = fmaxf(bm_lo, fmaxf(sc[n][0], sc[n][1]));
            bm_hi = fmaxf(bm_hi, fmaxf(sc[n][2], sc[n][3]));
        }
        bm_lo = fmaxf(bm_lo, __shfl_xor_sync(0xffffffffu, bm_lo, 1));
        bm_lo = fmaxf(bm_lo, __shfl_xor_sync(0xffffffffu, bm_lo, 2));
        bm_hi = fmaxf(bm_hi, __shfl_xor_sync(0xffffffffu, bm_hi, 1));
        bm_hi = fmaxf(bm_hi, __shfl_xor_sync(0xffffffffu, bm_hi, 2));
        const float mn_lo = fmaxf(m_lo, bm_lo);
        const float mn_hi = fmaxf(m_hi, bm_hi);
        const float f_lo = __expf(m_lo - mn_lo);
        const float f_hi = __expf(m_hi - mn_hi);
        m_lo = mn_lo; m_hi = mn_hi;

        float ps_lo = 0.f, ps_hi = 0.f;
#pragma unroll
        for (int n = 0; n < 8; n++) {
            sc[n][0] = __expf(sc[n][0] - mn_lo);
            sc[n][1] = __expf(sc[n][1] - mn_lo);
            sc[n][2] = __expf(sc[n][2] - mn_hi);
            sc[n][3] = __expf(sc[n][3] - mn_hi);
            ps_lo += sc[n][0] + sc[n][1];
            ps_hi += sc[n][2] + sc[n][3];
        }
        ps_lo += __shfl_xor_sync(0xffffffffu, ps_lo, 1);
        ps_lo += __shfl_xor_sync(0xffffffffu, ps_lo, 2);
        ps_hi += __shfl_xor_sync(0xffffffffu, ps_hi, 1);
        ps_hi += __shfl_xor_sync(0xffffffffu, ps_hi, 2);
        l_lo = l_lo * f_lo + ps_lo;
        l_hi = l_hi * f_hi + ps_hi;

#pragma unroll
        for (int n = 0; n < 8; n++) {
            oa[n][0] *= f_lo; oa[n][1] *= f_lo;
            oa[n][2] *= f_hi; oa[n][3] *= f_hi;
        }

        // ---- write P to smem (warp-private rows; tf32-rounded) ----
        {
            float* prow_lo = Qs + (w * 16 + (lane >> 2)) * AT_STRIDE + (lane & 3) * 2;
            float* prow_hi = prow_lo + 8 * AT_STRIDE;
#pragma unroll
            for (int n = 0; n < 8; n++) {
                float2 p0; p0.x = tf32r(sc[n][0]); p0.y = tf32r(sc[n][1]);
                float2 p1; p1.x = tf32r(sc[n][2]); p1.y = tf32r(sc[n][3]);
                *(float2*)(prow_lo + n * 8) = p0;
                *(float2*)(prow_hi + n * 8) = p1;
            }
        }
        __syncwarp();

        // ---- O += P @ V ----
#pragma unroll
        for (int s = 0; s < 8; s++) {
            uint32_t ap[4];
            ldsm4(ap, uQs + aoff + s * 32);
#pragma unroll
            for (int p = 0; p < 4; p++) {
                uint32_t r4[4];
                ldsm4(r4, uVt + boff[p] + s * 32);
                uint32_t b0[2] = { r4[0], r4[1] };
                uint32_t b1[2] = { r4[2], r4[3] };
                mma8(oa[2 * p], ap, b0);
                mma8(oa[2 * p + 1], ap, b1);
            }
        }
    }

    // ---- epilogue ----
    const float inv_lo = 1.f / l_lo, inv_hi = 1.f / l_hi;
    float* orow_lo = o + (bL + grow_lo) * DMODEL + h * HDIM + (lane & 3) * 2;
    float* orow_hi = o + (bL + grow_hi) * DMODEL + h * HDIM + (lane & 3) * 2;
#pragma unroll
    for (int n = 0; n < 8; n++) {
        float2 v0; v0.x = tf32r(oa[n][0] * inv_lo); v0.y = tf32r(oa[n][1] * inv_lo);
        float2 v1; v1.x = tf32r(oa[n][2] * inv_hi); v1.y = tf32r(oa[n][3] * inv_hi);
        *(float2*)(orow_lo + n * 8) = v0;
        *(float2*)(orow_hi + n * 8) = v1;
    }
}

// ---------------- launcher ----------------
extern "C" void kernel_launch(void* const* d_in, const int* in_sizes, int n_in,
                              void* d_out, int out_size)
{
    const float* x     = (const float*)d_in[0];
    const float* w_qkv = (const float*)d_in[1];
    const float* b_qkv = (const float*)d_in[2];
    const float* w_out = (const float*)d_in[3];
    const float* b_out = (const float*)d_in[4];
    const float* w_fc1 = (const float*)d_in[5];
    const float* b_fc1 = (const float*)d_in[6];
    const float* w_fc2 = (const float*)d_in[7];
    const float* b_fc2 = (const float*)d_in[8];
    const float* ln1_g = (const float*)d_in[9];
    const float* ln1_b = (const float*)d_in[10];
    const float* ln2_g = (const float*)d_in[11];
    const float* ln2_b = (const float*)d_in[12];
    float* out = (float*)d_out;

    float *h, *qkv, *o, *x1, *fc1, *wT;
    cudaGetSymbolAddress((void**)&h,   g_h);
    cudaGetSymbolAddress((void**)&qkv, g_qkv);
    cudaGetSymbolAddress((void**)&o,   g_o);
    cudaGetSymbolAddress((void**)&x1,  g_x1);
    cudaGetSymbolAddress((void**)&fc1, g_fc1);
    cudaGetSymbolAddress((void**)&wT,  g_wT);

    float* wqkvT = wT;
    float* woutT = wqkvT + 3072 * 1024;
    float* wfc1T = woutT + 1024 * 1024;
    float* wfc2T = wfc1T + 4096 * 1024;

    cudaFuncSetAttribute(sgemm_tc<0>, cudaFuncAttributeMaxDynamicSharedMemorySize, GEMM_SMEM);
    cudaFuncSetAttribute(sgemm_tc<1>, cudaFuncAttributeMaxDynamicSharedMemorySize, GEMM_SMEM);
    cudaFuncSetAttribute(sgemm_tc<2>, cudaFuncAttributeMaxDynamicSharedMemorySize, GEMM_SMEM);
    cudaFuncSetAttribute(attn_tc_kernel, cudaFuncAttributeMaxDynamicSharedMemorySize, ATT_SMEM);

    // 0) transpose weights
    transpose_kernel<<<dim3(D3 / 32,    DMODEL / 32), 256>>>(w_qkv, wqkvT, DMODEL, D3);
    transpose_kernel<<<dim3(DMODEL / 32, DMODEL / 32), 256>>>(w_out, woutT, DMODEL, DMODEL);
    transpose_kernel<<<dim3(INNER / 32,  DMODEL / 32), 256>>>(w_fc1, wfc1T, DMODEL, INNER);
    transpose_kernel<<<dim3(DMODEL / 32, INNER / 32), 256>>>(w_fc2, wfc2T, INNER, DMODEL);

    // 1) LN1
    ln_kernel<<<MROWS, 256>>>(x, ln1_g, ln1_b, h);

    // 2) QKV projection
    sgemm_tc<0><<<dim3(D3 / 128, MROWS / 128), 256, GEMM_SMEM>>>(
        h, wqkvT, b_qkv, nullptr, qkv, MROWS, D3, DMODEL);

    // 3) causal attention (tensor cores)
    attn_tc_kernel<<<dim3(SEQ / 128, BATCH * NHEAD), 256, ATT_SMEM>>>(qkv, o);

    // 4) out projection + residual
    sgemm_tc<1><<<dim3(DMODEL / 128, MROWS / 128), 256, GEMM_SMEM>>>(
        o, woutT, b_out, x, x1, MROWS, DMODEL, DMODEL);

    // 5) LN2
    ln_kernel<<<MROWS, 256>>>(x1, ln2_g, ln2_b, h);

    // 6) FC1 + exact GELU
    sgemm_tc<2><<<dim3(INNER / 128, MROWS / 128), 256, GEMM_SMEM>>>(
        h, wfc1T, b_fc1, nullptr, fc1, MROWS, INNER, DMODEL);

    // 7) FC2 + residual -> out
    sgemm_tc<1><<<dim3(DMODEL / 128, MROWS / 128), 256, GEMM_SMEM>>>(
        fc1, wfc2T, b_fc2, x1, out, MROWS, DMODEL, INNER);
}

// round 5
// speedup vs baseline: 4.9742x; 1.0100x over previous
#include <cuda_runtime.h>
#include <cuda_bf16.h>
#include <math.h>
#include <cstdint>

// Problem constants
#define BATCH 2
#define SEQ   2048
#define MROWS (BATCH*SEQ)       // 4096
#define DMODEL 1024
#define D3    (3*DMODEL)        // 3072
#define INNER (4*DMODEL)        // 4096
#define NHEAD 16
#define HDIM  64

// ---------------- scratch (device globals; no allocations allowed) ----------
__device__ float g_h  [MROWS*DMODEL];
__device__ float g_qkv[MROWS*D3];
__device__ float g_o  [MROWS*DMODEL];
__device__ float g_x1 [MROWS*DMODEL];
__device__ float g_fc1[MROWS*INNER];
__device__ float g_wT [12*1024*1024];   // transposed weights

// ---------------- helpers ----------------
__device__ __forceinline__ uint32_t smem_u32(const void* p) {
    uint32_t a;
    asm("{ .reg .u64 t; cvta.to.shared.u64 t, %1; cvt.u32.u64 %0, t; }" : "=r"(a) : "l"(p));
    return a;
}
__device__ __forceinline__ float tf32r(float x) {
    float y;
    asm("cvt.rna.tf32.f32 %0, %1;" : "=f"(y) : "f"(x));
    return y;
}
#define SW128(x) ((x) ^ (((x) >> 3) & 0x70))
#define CP16(sa, ga) \
    asm volatile("cp.async.cg.shared.global [%0], [%1], 16;" :: "r"(sa), "l"(ga) : "memory")

__device__ __forceinline__ void ldsm4(uint32_t* r, uint32_t a) {
    asm volatile("ldmatrix.sync.aligned.m8n8.x4.shared.b16 {%0,%1,%2,%3}, [%4];"
        : "=r"(r[0]), "=r"(r[1]), "=r"(r[2]), "=r"(r[3]) : "r"(a));
}
__device__ __forceinline__ void mma8(float* d, const uint32_t* a, const uint32_t* b) {
    asm volatile("mma.sync.aligned.m16n8k8.row.col.f32.tf32.tf32.f32 "
        "{%0,%1,%2,%3}, {%4,%5,%6,%7}, {%8,%9}, {%0,%1,%2,%3};"
        : "+f"(d[0]), "+f"(d[1]), "+f"(d[2]), "+f"(d[3])
        : "r"(a[0]), "r"(a[1]), "r"(a[2]), "r"(a[3]), "r"(b[0]), "r"(b[1]));
}

// ---------------- transpose (+ tf32 round): dst[C,R] = tf32(src[R,C]^T) -----
__global__ __launch_bounds__(256) void transpose_kernel(
    const float* __restrict__ src, float* __restrict__ dst, int R, int C)
{
    __shared__ float tile[32][33];
    const int c0 = blockIdx.x * 32, r0 = blockIdx.y * 32;
    const int tx = threadIdx.x & 31, ty = threadIdx.x >> 5;
#pragma unroll
    for (int i = 0; i < 4; i++)
        tile[ty + 8 * i][tx] = src[(size_t)(r0 + ty + 8 * i) * C + c0 + tx];
    __syncthreads();
#pragma unroll
    for (int i = 0; i < 4; i++)
        dst[(size_t)(c0 + ty + 8 * i) * R + r0 + tx] = tf32r(tile[tx][ty + 8 * i]);
}

// ---------------- tensor-core GEMM: C = A[M,K] @ Bt[N,K]^T + bias ----------
// CTA tile 256x128, 8 warps (4x2), warp tile 64x64, 3-stage cp.async pipeline.
#define G_ABYTES 32768
#define G_BBYTES 16384
#define G_STAGE  (G_ABYTES + G_BBYTES)   // 49152
#define GEMM_SMEM (3 * G_STAGE)          // 147456

template<int EPI>
__global__ __launch_bounds__(256, 1) void sgemm_tc(
    const float* __restrict__ A, const float* __restrict__ Bt,
    const float* __restrict__ bias, const float* __restrict__ res,
    float* __restrict__ C, int M, int N, int K)
{
    extern __shared__ char smem[];
    const uint32_t sb = smem_u32(smem);
    const int tid = threadIdx.x, lane = tid & 31, wid = tid >> 5;
    const int warp_m = wid >> 1, warp_n = wid & 1;
    const int m0 = blockIdx.y * 256, n0 = blockIdx.x * 128;
    const int mb = warp_m * 64, nb = warp_n * 64;

    // cp.async source/dest mapping (per thread)
    const int lr = tid >> 3, lc = tid & 7;          // A/B: row block, float4 col

    const int u = lane >> 3, ur = lane & 7;
    uint32_t aoff[4], boff[4];
#pragma unroll
    for (int i = 0; i < 4; i++)
        aoff[i] = (uint32_t)(mb + i * 16 + (u & 1) * 8 + ur) * 128 + (u >> 1) * 16;
#pragma unroll
    for (int p = 0; p < 4; p++)
        boff[p] = (uint32_t)(nb + p * 16 + (u >> 1) * 8 + ur) * 128 + (u & 1) * 16;

    float acc[4][8][4];
#pragma unroll
    for (int i = 0; i < 4; i++)
#pragma unroll
        for (int j = 0; j < 8; j++)
#pragma unroll
            for (int q = 0; q < 4; q++) acc[i][j][q] = 0.f;

    const int nk = K >> 5;

    // ---- stage-load helper (as macro to keep everything in registers) ----
#define G_ISSUE(stg, t)                                                        \
    do {                                                                       \
        const uint32_t sa_ = sb + (stg) * G_STAGE;                             \
        const uint32_t sbB_ = sa_ + G_ABYTES;                                  \
        _Pragma("unroll")                                                      \
        for (int i_ = 0; i_ < 8; i_++) {                                       \
            const int r_ = lr + 32 * i_;                                       \
            const uint32_t so_ = SW128((uint32_t)r_ * 128 + lc * 16);          \
            CP16(sa_ + so_, A + (size_t)(m0 + r_) * K + (t) * 32 + lc * 4);    \
        }                                                                      \
        _Pragma("unroll")                                                      \
        for (int i_ = 0; i_ < 4; i_++) {                                       \
            const int r_ = lr + 32 * i_;                                       \
            const uint32_t so_ = SW128((uint32_t)r_ * 128 + lc * 16);          \
            CP16(sbB_ + so_, Bt + (size_t)(n0 + r_) * K + (t) * 32 + lc * 4);  \
        }                                                                      \
        asm volatile("cp.async.commit_group;" ::: "memory");                   \
    } while (0)

    // prologue: stages 0 and 1 (nk >= 32 always here)
    G_ISSUE(0, 0);
    G_ISSUE(1, 1);

    int stage = 0;
    for (int t = 0; t < nk; t++) {
        if (t + 1 < nk) {
            asm volatile("cp.async.wait_group 1;" ::: "memory");
        } else {
            asm volatile("cp.async.wait_group 0;" ::: "memory");
        }
        __syncthreads();

        if (t + 2 < nk) {
            const int ns = (stage + 2 >= 3) ? stage - 1 : stage + 2;
            G_ISSUE(ns, t + 2);
        }

        const uint32_t sa = sb + stage * G_STAGE;
        const uint32_t sbB = sa + G_ABYTES;
#pragma unroll
        for (int s = 0; s < 4; s++) {
            uint32_t af[4][4], bf[8][2];
#pragma unroll
            for (int i = 0; i < 4; i++)
                ldsm4(af[i], sa + SW128(aoff[i] + s * 32));
#pragma unroll
            for (int p = 0; p < 4; p++) {
                uint32_t r4[4];
                ldsm4(r4, sbB + SW128(boff[p] + s * 32));
                bf[2 * p][0] = r4[0]; bf[2 * p][1] = r4[1];
                bf[2 * p + 1][0] = r4[2]; bf[2 * p + 1][1] = r4[3];
            }
#pragma unroll
            for (int i = 0; i < 4; i++)
#pragma unroll
                for (int j = 0; j < 8; j++) mma8(acc[i][j], af[i], bf[j]);
        }
        stage = (stage + 1 >= 3) ? 0 : stage + 1;
    }
#undef G_ISSUE

    // ---- epilogue ----
    const int r0 = m0 + mb + (lane >> 2);
    const int c0 = n0 + nb + (lane & 3) * 2;
#pragma unroll
    for (int i = 0; i < 4; i++) {
#pragma unroll
        for (int j = 0; j < 8; j++) {
            const int col = c0 + j * 8;
            const float bx = bias[col], by = bias[col + 1];
#pragma unroll
            for (int hh = 0; hh < 2; hh++) {
                const int row = r0 + i * 16 + hh * 8;
                float vx = acc[i][j][hh * 2 + 0] + bx;
                float vy = acc[i][j][hh * 2 + 1] + by;
                if (EPI == 1) {
                    const float2 rr = *(const float2*)(res + (size_t)row * N + col);
                    vx += rr.x; vy += rr.y;
                }
                if (EPI == 2) {
                    vx = tf32r(0.5f * vx * (1.f + erff(vx * 0.70710678118654752f)));
                    vy = tf32r(0.5f * vy * (1.f + erff(vy * 0.70710678118654752f)));
                }
                float2 v; v.x = vx; v.y = vy;
                *(float2*)(C + (size_t)row * N + col) = v;
            }
        }
    }
}

// ---------------- LayerNorm (tf32-rounded output; feeds GEMMs) --------
__global__ __launch_bounds__(256) void ln_kernel(
    const float* __restrict__ x, const float* __restrict__ g,
    const float* __restrict__ b, float* __restrict__ out)
{
    __shared__ float red[16];
    const long row = blockIdx.x;
    const float* xr = x + row * DMODEL;
    const int tid = threadIdx.x;

    float v[4];
    float s1 = 0.f, s2 = 0.f;
#pragma unroll
    for (int i = 0; i < 4; i++) {
        v[i] = xr[tid + 256 * i];
        s1 += v[i];
        s2 += v[i] * v[i];
    }
#pragma unroll
    for (int o = 16; o; o >>= 1) {
        s1 += __shfl_xor_sync(0xffffffffu, s1, o);
        s2 += __shfl_xor_sync(0xffffffffu, s2, o);
    }
    if ((tid & 31) == 0) { red[tid >> 5] = s1; red[8 + (tid >> 5)] = s2; }
    __syncthreads();
    if (tid < 32) {
        float a = (tid < 8) ? red[tid] : 0.f;
        float c = (tid < 8) ? red[8 + tid] : 0.f;
#pragma unroll
        for (int o = 4; o; o >>= 1) {
            a += __shfl_xor_sync(0xffffffffu, a, o);
            c += __shfl_xor_sync(0xffffffffu, c, o);
        }
        if (tid == 0) { red[0] = a; red[8] = c; }
    }
    __syncthreads();
    const float mu  = red[0] * (1.f / DMODEL);
    const float var = red[8] * (1.f / DMODEL) - mu * mu;
    const float r   = rsqrtf(var + 1e-5f);
#pragma unroll
    for (int i = 0; i < 4; i++) {
        const int c = tid + 256 * i;
        out[row * DMODEL + c] = tf32r((v[i] - mu) * r * g[c] + b[c]);
    }
}

// ---------------- tensor-core flash attention (tf32 mma) --------------------
#define AT_STRIDE 68
#define ATT_SMEM ((128 + 64 + 64) * AT_STRIDE * 4)   // 69632

__global__ __launch_bounds__(256) void attn_tc_kernel(
    const float* __restrict__ qkv, float* __restrict__ o)
{
    extern __shared__ float sm[];
    float* Qs = sm;                                  // [128][68], reused as Ps
    float* Ks = Qs + 128 * AT_STRIDE;                // [64][68]
    float* Vt = Ks + 64 * AT_STRIDE;                 // [64][68] (hd-major)
    const uint32_t uQs = smem_u32(Qs), uKs = smem_u32(Ks), uVt = smem_u32(Vt);

    const int tid = threadIdx.x, lane = tid & 31, w = tid >> 5;
    const int bh = blockIdx.y;
    const int b = bh >> 4, h = bh & 15;
    const int qb = (int)gridDim.x - 1 - (int)blockIdx.x;   // heavy tiles first
    const int q0 = qb * 128;
    const size_t bL = (size_t)b * SEQ;

    const int u = lane >> 3, ur = lane & 7;
    const uint32_t aoff = (uint32_t)(w * 16 + (u & 1) * 8 + ur) * (AT_STRIDE * 4) + (u >> 1) * 16;
    uint32_t boff[4];
#pragma unroll
    for (int p = 0; p < 4; p++)
        boff[p] = (uint32_t)(p * 16 + (u >> 1) * 8 + ur) * (AT_STRIDE * 4) + (u & 1) * 16;

    // ---- load Q tile (tf32-rounded) ----
#pragma unroll
    for (int i = 0; i < 8; i++) {
        const int idx = tid + 256 * i;
        const int r = idx >> 4, c = idx & 15;
        const float4 q4 = *(const float4*)(qkv + (bL + q0 + r) * D3 + h * HDIM + c * 4);
        float* dst = Qs + r * AT_STRIDE + c * 4;
        dst[0] = tf32r(q4.x); dst[1] = tf32r(q4.y);
        dst[2] = tf32r(q4.z); dst[3] = tf32r(q4.w);
    }
    __syncthreads();

    uint32_t qf[8][4];
#pragma unroll
    for (int s = 0; s < 8; s++) ldsm4(qf[s], uQs + aoff + s * 32);

    float oa[8][4];
#pragma unroll
    for (int n = 0; n < 8; n++)
#pragma unroll
        for (int q = 0; q < 4; q++) oa[n][q] = 0.f;
    float m_lo = -1e30f, m_hi = -1e30f, l_lo = 0.f, l_hi = 0.f;

    const int grow_lo = q0 + w * 16 + (lane >> 2);
    const int grow_hi = grow_lo + 8;
    const int nkb = 2 * qb + 2;

    for (int kb = 0; kb < nkb; kb++) {
        __syncthreads();
#pragma unroll
        for (int i = 0; i < 4; i++) {
            const int idx = tid + 256 * i;
            const int r = idx >> 4, c = idx & 15;
            const float* kp = qkv + (bL + kb * 64 + r) * D3 + DMODEL + h * HDIM + c * 4;
            const float4 k4 = *(const float4*)kp;
            float* kd = Ks + r * AT_STRIDE + c * 4;
            kd[0] = tf32r(k4.x); kd[1] = tf32r(k4.y);
            kd[2] = tf32r(k4.z); kd[3] = tf32r(k4.w);
            const float4 v4 = *(const float4*)(kp + DMODEL);
            Vt[(c * 4 + 0) * AT_STRIDE + r] = tf32r(v4.x);
            Vt[(c * 4 + 1) * AT_STRIDE + r] = tf32r(v4.y);
            Vt[(c * 4 + 2) * AT_STRIDE + r] = tf32r(v4.z);
            Vt[(c * 4 + 3) * AT_STRIDE + r] = tf32r(v4.w);
        }
        __syncthreads();

        float sc[8][4];
#pragma unroll
        for (int n = 0; n < 8; n++)
#pragma unroll
            for (int q = 0; q < 4; q++) sc[n][q] = 0.f;
#pragma unroll
        for (int s = 0; s < 8; s++) {
            uint32_t bf[8][2];
#pragma unroll
            for (int p = 0; p < 4; p++) {
                uint32_t r4[4];
                ldsm4(r4, uKs + boff[p] + s * 32);
                bf[2 * p][0] = r4[0]; bf[2 * p][1] = r4[1];
                bf[2 * p + 1][0] = r4[2]; bf[2 * p + 1][1] = r4[3];
            }
#pragma unroll
            for (int n = 0; n < 8; n++) mma8(sc[n], qf[s], bf[n]);
        }

        const bool need_mask = (kb >= 2 * qb);
        const int c0g = kb * 64 + (lane & 3) * 2;
#pragma unroll
        for (int n = 0; n < 8; n++) {
            const int col0 = c0g + n * 8, col1 = col0 + 1;
            float s0 = sc[n][0] * 0.125f, s1 = sc[n][1] * 0.125f;
            float s2 = sc[n][2] * 0.125f, s3 = sc[n][3] * 0.125f;
            if (need_mask) {
                if (col0 > grow_lo) s0 = -1e30f;
                if (col1 > grow_lo) s1 = -1e30f;
                if (col0 > grow_hi) s2 = -1e30f;
                if (col1 > grow_hi) s3 = -1e30f;
            }
            sc[n][0] = s0; sc[n][1] = s1; sc[n][2] = s2; sc[n][3] = s3;
        }

        float bm_lo = -1e30f, bm_hi = -1e30f;
#pragma unroll
        for (int n = 0; n < 8; n++) {
            bm_lo = fmaxf(bm_lo, fmaxf(sc[n][0], sc[n][1]));
            bm_hi = fmaxf(bm_hi, fmaxf(sc[n][2], sc[n][3]));
        }
        bm_lo = fmaxf(bm_lo, __shfl_xor_sync(0xffffffffu, bm_lo, 1));
        bm_lo = fmaxf(bm_lo, __shfl_xor_sync(0xffffffffu, bm_lo, 2));
        bm_hi = fmaxf(bm_hi, __shfl_xor_sync(0xffffffffu, bm_hi, 1));
        bm_hi = fmaxf(bm_hi, __shfl_xor_sync(0xffffffffu, bm_hi, 2));
        const float mn_lo = fmaxf(m_lo, bm_lo);
        const float mn_hi = fmaxf(m_hi, bm_hi);
        const float f_lo = __expf(m_lo - mn_lo);
        const float f_hi = __expf(m_hi - mn_hi);
        m_lo = mn_lo; m_hi = mn_hi;

        float ps_lo = 0.f, ps_hi = 0.f;
#pragma unroll
        for (int n = 0; n < 8; n++) {
            sc[n][0] = __expf(sc[n][0] - mn_lo);
            sc[n][1] = __expf(sc[n][1] - mn_lo);
            sc[n][2] = __expf(sc[n][2] - mn_hi);
            sc[n][3] = __expf(sc[n][3] - mn_hi);
            ps_lo += sc[n][0] + sc[n][1];
            ps_hi += sc[n][2] + sc[n][3];
        }
        ps_lo += __shfl_xor_sync(0xffffffffu, ps_lo, 1);
        ps_lo += __shfl_xor_sync(0xffffffffu, ps_lo, 2);
        ps_hi += __shfl_xor_sync(0xffffffffu, ps_hi, 1);
        ps_hi += __shfl_xor_sync(0xffffffffu, ps_hi, 2);
        l_lo = l_lo * f_lo + ps_lo;
        l_hi = l_hi * f_hi + ps_hi;

#pragma unroll
        for (int n = 0; n < 8; n++) {
            oa[n][0] *= f_lo; oa[n][1] *= f_lo;
            oa[n][2] *= f_hi; oa[n][3] *= f_hi;
        }

        {
            float* prow_lo = Qs + (w * 16 + (lane >> 2)) * AT_STRIDE + (lane & 3) * 2;
            float* prow_hi = prow_lo + 8 * AT_STRIDE;
#pragma unroll
            for (int n = 0; n < 8; n++) {
                float2 p0; p0.x = tf32r(sc[n][0]); p0.y = tf32r(sc[n][1]);
                float2 p1; p1.x = tf32r(sc[n][2]); p1.y = tf32r(sc[n][3]);
                *(float2*)(prow_lo + n * 8) = p0;
                *(float2*)(prow_hi + n * 8) = p1;
            }
        }
        __syncwarp();

#pragma unroll
        for (int s = 0; s < 8; s++) {
            uint32_t ap[4];
            ldsm4(ap, uQs + aoff + s * 32);
#pragma unroll
            for (int p = 0; p < 4; p++) {
                uint32_t r4[4];
                ldsm4(r4, uVt + boff[p] + s * 32);
                uint32_t b0[2] = { r4[0], r4[1] };
                uint32_t b1[2] = { r4[2], r4[3] };
                mma8(oa[2 * p], ap, b0);
                mma8(oa[2 * p + 1], ap, b1);
            }
        }
    }

    const float inv_lo = 1.f / l_lo, inv_hi = 1.f / l_hi;
    float* orow_lo = o + (bL + grow_lo) * DMODEL + h * HDIM + (lane & 3) * 2;
    float* orow_hi = o + (bL + grow_hi) * DMODEL + h * HDIM + (lane & 3) * 2;
#pragma unroll
    for (int n = 0; n < 8; n++) {
        float2 v0; v0.x = tf32r(oa[n][0] * inv_lo); v0.y = tf32r(oa[n][1] * inv_lo);
        float2 v1; v1.x = tf32r(oa[n][2] * inv_hi); v1.y = tf32r(oa[n][3] * inv_hi);
        *(float2*)(orow_lo + n * 8) = v0;
        *(float2*)(orow_hi + n * 8) = v1;
    }
}

// ---------------- launcher ----------------
extern "C" void kernel_launch(void* const* d_in, const int* in_sizes, int n_in,
                              void* d_out, int out_size)
{
    const float* x     = (const float*)d_in[0];
    const float* w_qkv = (const float*)d_in[1];
    const float* b_qkv = (const float*)d_in[2];
    const float* w_out = (const float*)d_in[3];
    const float* b_out = (const float*)d_in[4];
    const float* w_fc1 = (const float*)d_in[5];
    const float* b_fc1 = (const float*)d_in[6];
    const float* w_fc2 = (const float*)d_in[7];
    const float* b_fc2 = (const float*)d_in[8];
    const float* ln1_g = (const float*)d_in[9];
    const float* ln1_b = (const float*)d_in[10];
    const float* ln2_g = (const float*)d_in[11];
    const float* ln2_b = (const float*)d_in[12];
    float* out = (float*)d_out;

    float *h, *qkv, *o, *x1, *fc1, *wT;
    cudaGetSymbolAddress((void**)&h,   g_h);
    cudaGetSymbolAddress((void**)&qkv, g_qkv);
    cudaGetSymbolAddress((void**)&o,   g_o);
    cudaGetSymbolAddress((void**)&x1,  g_x1);
    cudaGetSymbolAddress((void**)&fc1, g_fc1);
    cudaGetSymbolAddress((void**)&wT,  g_wT);

    float* wqkvT = wT;
    float* woutT = wqkvT + 3072 * 1024;
    float* wfc1T = woutT + 1024 * 1024;
    float* wfc2T = wfc1T + 4096 * 1024;

    cudaFuncSetAttribute(sgemm_tc<0>, cudaFuncAttributeMaxDynamicSharedMemorySize, GEMM_SMEM);
    cudaFuncSetAttribute(sgemm_tc<1>, cudaFuncAttributeMaxDynamicSharedMemorySize, GEMM_SMEM);
    cudaFuncSetAttribute(sgemm_tc<2>, cudaFuncAttributeMaxDynamicSharedMemorySize, GEMM_SMEM);
    cudaFuncSetAttribute(attn_tc_kernel, cudaFuncAttributeMaxDynamicSharedMemorySize, ATT_SMEM);

    // 0) transpose weights
    transpose_kernel<<<dim3(D3 / 32,    DMODEL / 32), 256>>>(w_qkv, wqkvT, DMODEL, D3);
    transpose_kernel<<<dim3(DMODEL / 32, DMODEL / 32), 256>>>(w_out, woutT, DMODEL, DMODEL);
    transpose_kernel<<<dim3(INNER / 32,  DMODEL / 32), 256>>>(w_fc1, wfc1T, DMODEL, INNER);
    transpose_kernel<<<dim3(DMODEL / 32, INNER / 32), 256>>>(w_fc2, wfc2T, INNER, DMODEL);

    // 1) LN1
    ln_kernel<<<MROWS, 256>>>(x, ln1_g, ln1_b, h);

    // 2) QKV projection
    sgemm_tc<0><<<dim3(D3 / 128, MROWS / 256), 256, GEMM_SMEM>>>(
        h, wqkvT, b_qkv, nullptr, qkv, MROWS, D3, DMODEL);

    // 3) causal attention (tensor cores)
    attn_tc_kernel<<<dim3(SEQ / 128, BATCH * NHEAD), 256, ATT_SMEM>>>(qkv, o);

    // 4) out projection + residual
    sgemm_tc<1><<<dim3(DMODEL / 128, MROWS / 256), 256, GEMM_SMEM>>>(
        o, woutT, b_out, x, x1, MROWS, DMODEL, DMODEL);

    // 5) LN2
    ln_kernel<<<MROWS, 256>>>(x1, ln2_g, ln2_b, h);

    // 6) FC1 + exact GELU
    sgemm_tc<2><<<dim3(INNER / 128, MROWS / 256), 256, GEMM_SMEM>>>(
        h, wfc1T, b_fc1, nullptr, fc1, MROWS, INNER, DMODEL);

    // 7) FC2 + residual -> out
    sgemm_tc<1><<<dim3(DMODEL / 128, MROWS / 256), 256, GEMM_SMEM>>>(
        fc1, wfc2T, b_fc2, x1, out, MROWS, DMODEL, INNER);
}

// round 6
// speedup vs baseline: 6.9780x; 1.4028x over previous
#include <cuda_runtime.h>
#include <cuda_fp16.h>
#include <cuda_bf16.h>
#include <math.h>
#include <cstdint>

// Problem constants
#define BATCH 2
#define SEQ   2048
#define MROWS (BATCH*SEQ)       // 4096
#define DMODEL 1024
#define D3    (3*DMODEL)        // 3072
#define INNER (4*DMODEL)        // 4096
#define NHEAD 16
#define HDIM  64

// ---------------- scratch (device globals; no allocations allowed) ----------
__device__ __half g_hh [MROWS*DMODEL];    // LN output (fp16, GEMM A operand)
__device__ float  g_qkv[MROWS*D3];        // QKV projection (fp32, attention input)
__device__ __half g_oh [MROWS*DMODEL];    // attention output (fp16)
__device__ float  g_x1 [MROWS*DMODEL];    // residual after attention (fp32)
__device__ __half g_fc1h[MROWS*INNER];    // FC1+GELU output (fp16)
__device__ __half g_wTh[12*1024*1024];    // transposed fp16 weights

// ---------------- helpers ----------------
__device__ __forceinline__ uint32_t smem_u32(const void* p) {
    uint32_t a;
    asm("{ .reg .u64 t; cvta.to.shared.u64 t, %1; cvt.u32.u64 %0, t; }" : "=r"(a) : "l"(p));
    return a;
}
__device__ __forceinline__ float tf32r(float x) {
    float y;
    asm("cvt.rna.tf32.f32 %0, %1;" : "=f"(y) : "f"(x));
    return y;
}
#define SW64(x) ((x) ^ (((x) >> 3) & 0x30))
#define CP16(sa, ga) \
    asm volatile("cp.async.cg.shared.global [%0], [%1], 16;" :: "r"(sa), "l"(ga) : "memory")

__device__ __forceinline__ void ldsm4(uint32_t* r, uint32_t a) {
    asm volatile("ldmatrix.sync.aligned.m8n8.x4.shared.b16 {%0,%1,%2,%3}, [%4];"
        : "=r"(r[0]), "=r"(r[1]), "=r"(r[2]), "=r"(r[3]) : "r"(a));
}
// fp16 MMA: D(16x8,f32) += A(16x16,f16) * B(8x16,f16)^T
__device__ __forceinline__ void mma16(float* d, const uint32_t* a, const uint32_t* b) {
    asm volatile("mma.sync.aligned.m16n8k16.row.col.f32.f16.f16.f32 "
        "{%0,%1,%2,%3}, {%4,%5,%6,%7}, {%8,%9}, {%0,%1,%2,%3};"
        : "+f"(d[0]), "+f"(d[1]), "+f"(d[2]), "+f"(d[3])
        : "r"(a[0]), "r"(a[1]), "r"(a[2]), "r"(a[3]), "r"(b[0]), "r"(b[1]));
}
// tf32 MMA (attention)
__device__ __forceinline__ void mma8(float* d, const uint32_t* a, const uint32_t* b) {
    asm volatile("mma.sync.aligned.m16n8k8.row.col.f32.tf32.tf32.f32 "
        "{%0,%1,%2,%3}, {%4,%5,%6,%7}, {%8,%9}, {%0,%1,%2,%3};"
        : "+f"(d[0]), "+f"(d[1]), "+f"(d[2]), "+f"(d[3])
        : "r"(a[0]), "r"(a[1]), "r"(a[2]), "r"(a[3]), "r"(b[0]), "r"(b[1]));
}

// ---------------- transpose to fp16: dst[C,R] = half(src[R,C]^T) ------------
__global__ __launch_bounds__(256) void transpose_kernel(
    const float* __restrict__ src, __half* __restrict__ dst, int R, int C)
{
    __shared__ float tile[32][33];
    const int c0 = blockIdx.x * 32, r0 = blockIdx.y * 32;
    const int tx = threadIdx.x & 31, ty = threadIdx.x >> 5;
#pragma unroll
    for (int i = 0; i < 4; i++)
        tile[ty + 8 * i][tx] = src[(size_t)(r0 + ty + 8 * i) * C + c0 + tx];
    __syncthreads();
#pragma unroll
    for (int i = 0; i < 4; i++)
        dst[(size_t)(c0 + ty + 8 * i) * R + r0 + tx] = __float2half(tile[tx][ty + 8 * i]);
}

// ---------------- fp16 tensor-core GEMM: C = A[M,K] @ Bt[N,K]^T + bias ------
// CTA tile 128x128, 8 warps (2x4) of 64x32, K-chunk = 32 halves (64B rows,
// SW64 swizzle), 4-stage cp.async pipeline. EPI: 0 bias, 1 bias+res, 2 GELU.
#define GS_ABYTES 8192
#define GS_STAGE  16384
#define GEMM_SMEM (4 * GS_STAGE)   // 65536

template<int EPI, typename CT>
__global__ __launch_bounds__(256) void hgemm_tc(
    const __half* __restrict__ A, const __half* __restrict__ Bt,
    const float* __restrict__ bias, const float* __restrict__ res,
    CT* __restrict__ C, int M, int N, int K)
{
    extern __shared__ char smem[];
    const uint32_t sb = smem_u32(smem);
    const int tid = threadIdx.x, lane = tid & 31, wid = tid >> 5;
    const int warp_m = wid >> 2, warp_n = wid & 3;
    const int m0 = blockIdx.y * 128, n0 = blockIdx.x * 128;
    const int mb = warp_m * 64, nb = warp_n * 32;

    // cp.async mapping: quarter-warp conflict-free (r = lane&7, c = lane>>3)
    const int cr = (wid * 8) + (lane & 7);   // base row 0..63 (+64 per pass)
    const int cc = lane >> 3;                // 16B chunk 0..3

    // ldmatrix per-lane offsets (raw, swizzle applied at use)
    const int u = lane >> 3, ur = lane & 7;
    uint32_t aoff[4], boff[2];
#pragma unroll
    for (int i = 0; i < 4; i++)
        aoff[i] = (uint32_t)(mb + i * 16 + (u & 1) * 8 + ur) * 64 + (u >> 1) * 16;
#pragma unroll
    for (int p = 0; p < 2; p++)
        boff[p] = (uint32_t)(nb + p * 16 + (u >> 1) * 8 + ur) * 64 + (u & 1) * 16;

    float acc[4][4][4];
#pragma unroll
    for (int i = 0; i < 4; i++)
#pragma unroll
        for (int j = 0; j < 4; j++)
#pragma unroll
            for (int q = 0; q < 4; q++) acc[i][j][q] = 0.f;

    const int nk = K >> 5;   // chunks of 32 halves

#define H_ISSUE(t)                                                             \
    do {                                                                       \
        const uint32_t sa_ = sb + ((t) & 3) * GS_STAGE;                        \
        const uint32_t sbB_ = sa_ + GS_ABYTES;                                 \
        _Pragma("unroll")                                                      \
        for (int p_ = 0; p_ < 2; p_++) {                                       \
            const int r_ = cr + 64 * p_;                                       \
            const uint32_t so_ = SW64((uint32_t)r_ * 64 + cc * 16);            \
            CP16(sa_ + so_, A + (size_t)(m0 + r_) * K + (t) * 32 + cc * 8);    \
            CP16(sbB_ + so_, Bt + (size_t)(n0 + r_) * K + (t) * 32 + cc * 8);  \
        }                                                                      \
        asm volatile("cp.async.commit_group;" ::: "memory");                   \
    } while (0)

    H_ISSUE(0); H_ISSUE(1); H_ISSUE(2);

    for (int t = 0; t < nk; t++) {
        const int rem = nk - 1 - t;
        if (rem >= 2)       asm volatile("cp.async.wait_group 2;" ::: "memory");
        else if (rem == 1)  asm volatile("cp.async.wait_group 1;" ::: "memory");
        else                asm volatile("cp.async.wait_group 0;" ::: "memory");
        __syncthreads();

        if (t + 3 < nk) H_ISSUE(t + 3);

        const uint32_t sa = sb + (t & 3) * GS_STAGE;
        const uint32_t sbB = sa + GS_ABYTES;
#pragma unroll
        for (int s = 0; s < 2; s++) {          // 2 x k16 steps per chunk
            uint32_t af[4][4], bf[4][2];
#pragma unroll
            for (int i = 0; i < 4; i++)
                ldsm4(af[i], sa + SW64(aoff[i] + s * 32));
#pragma unroll
            for (int p = 0; p < 2; p++) {
                uint32_t r4[4];
                ldsm4(r4, sbB + SW64(boff[p] + s * 32));
                bf[2 * p][0] = r4[0]; bf[2 * p][1] = r4[1];
                bf[2 * p + 1][0] = r4[2]; bf[2 * p + 1][1] = r4[3];
            }
#pragma unroll
            for (int i = 0; i < 4; i++)
#pragma unroll
                for (int j = 0; j < 4; j++) mma16(acc[i][j], af[i], bf[j]);
        }
        __syncthreads();
    }
#undef H_ISSUE

    // ---- epilogue ----
    const int r0 = m0 + mb + (lane >> 2);
    const int c0 = n0 + nb + (lane & 3) * 2;
#pragma unroll
    for (int i = 0; i < 4; i++) {
#pragma unroll
        for (int j = 0; j < 4; j++) {
            const int col = c0 + j * 8;
            const float bx = bias[col], by = bias[col + 1];
#pragma unroll
            for (int hh = 0; hh < 2; hh++) {
                const int row = r0 + i * 16 + hh * 8;
                float vx = acc[i][j][hh * 2 + 0] + bx;
                float vy = acc[i][j][hh * 2 + 1] + by;
                if (EPI == 1) {
                    const float2 rr = *(const float2*)(res + (size_t)row * N + col);
                    vx += rr.x; vy += rr.y;
                }
                if (EPI == 2) {
                    vx = 0.5f * vx * (1.f + erff(vx * 0.70710678118654752f));
                    vy = 0.5f * vy * (1.f + erff(vy * 0.70710678118654752f));
                }
                CT* cp = C + (size_t)row * N + col;
                if (sizeof(CT) == 2) {
                    __half2 hv = __floats2half2_rn(vx, vy);
                    *(__half2*)cp = hv;
                } else {
                    float2 v; v.x = vx; v.y = vy;
                    *(float2*)cp = v;
                }
            }
        }
    }
}

// ---------------- LayerNorm (fp16 output; feeds GEMM A) --------------------
__global__ __launch_bounds__(256) void ln_kernel(
    const float* __restrict__ x, const float* __restrict__ g,
    const float* __restrict__ b, __half* __restrict__ out)
{
    __shared__ float red[16];
    const long row = blockIdx.x;
    const float* xr = x + row * DMODEL;
    const int tid = threadIdx.x;

    float v[4];
    float s1 = 0.f, s2 = 0.f;
#pragma unroll
    for (int i = 0; i < 4; i++) {
        v[i] = xr[tid + 256 * i];
        s1 += v[i];
        s2 += v[i] * v[i];
    }
#pragma unroll
    for (int o = 16; o; o >>= 1) {
        s1 += __shfl_xor_sync(0xffffffffu, s1, o);
        s2 += __shfl_xor_sync(0xffffffffu, s2, o);
    }
    if ((tid & 31) == 0) { red[tid >> 5] = s1; red[8 + (tid >> 5)] = s2; }
    __syncthreads();
    if (tid < 32) {
        float a = (tid < 8) ? red[tid] : 0.f;
        float c = (tid < 8) ? red[8 + tid] : 0.f;
#pragma unroll
        for (int o = 4; o; o >>= 1) {
            a += __shfl_xor_sync(0xffffffffu, a, o);
            c += __shfl_xor_sync(0xffffffffu, c, o);
        }
        if (tid == 0) { red[0] = a; red[8] = c; }
    }
    __syncthreads();
    const float mu  = red[0] * (1.f / DMODEL);
    const float var = red[8] * (1.f / DMODEL) - mu * mu;
    const float r   = rsqrtf(var + 1e-5f);
#pragma unroll
    for (int i = 0; i < 4; i++) {
        const int c = tid + 256 * i;
        out[row * DMODEL + c] = __float2half((v[i] - mu) * r * g[c] + b[c]);
    }
}

// ---------------- tensor-core flash attention (tf32 mma) --------------------
#define AT_STRIDE 68
#define ATT_SMEM ((128 + 64 + 64) * AT_STRIDE * 4)   // 69632

__global__ __launch_bounds__(256) void attn_tc_kernel(
    const float* __restrict__ qkv, __half* __restrict__ o)
{
    extern __shared__ float sm[];
    float* Qs = sm;                                  // [128][68], reused as Ps
    float* Ks = Qs + 128 * AT_STRIDE;                // [64][68]
    float* Vt = Ks + 64 * AT_STRIDE;                 // [64][68] (hd-major)
    const uint32_t uQs = smem_u32(Qs), uKs = smem_u32(Ks), uVt = smem_u32(Vt);

    const int tid = threadIdx.x, lane = tid & 31, w = tid >> 5;
    const int bh = blockIdx.y;
    const int b = bh >> 4, h = bh & 15;
    const int qb = (int)gridDim.x - 1 - (int)blockIdx.x;   // heavy tiles first
    const int q0 = qb * 128;
    const size_t bL = (size_t)b * SEQ;

    const int u = lane >> 3, ur = lane & 7;
    const uint32_t aoff = (uint32_t)(w * 16 + (u & 1) * 8 + ur) * (AT_STRIDE * 4) + (u >> 1) * 16;
    uint32_t boff[4];
#pragma unroll
    for (int p = 0; p < 4; p++)
        boff[p] = (uint32_t)(p * 16 + (u >> 1) * 8 + ur) * (AT_STRIDE * 4) + (u & 1) * 16;

    // ---- load Q tile (tf32-rounded) ----
#pragma unroll
    for (int i = 0; i < 8; i++) {
        const int idx = tid + 256 * i;
        const int r = idx >> 4, c = idx & 15;
        const float4 q4 = *(const float4*)(qkv + (bL + q0 + r) * D3 + h * HDIM + c * 4);
        float* dst = Qs + r * AT_STRIDE + c * 4;
        dst[0] = tf32r(q4.x); dst[1] = tf32r(q4.y);
        dst[2] = tf32r(q4.z); dst[3] = tf32r(q4.w);
    }
    __syncthreads();

    uint32_t qf[8][4];
#pragma unroll
    for (int s = 0; s < 8; s++) ldsm4(qf[s], uQs + aoff + s * 32);

    float oa[8][4];
#pragma unroll
    for (int n = 0; n < 8; n++)
#pragma unroll
        for (int q = 0; q < 4; q++) oa[n][q] = 0.f;
    float m_lo = -1e30f, m_hi = -1e30f, l_lo = 0.f, l_hi = 0.f;

    const int grow_lo = q0 + w * 16 + (lane >> 2);
    const int grow_hi = grow_lo + 8;
    const int nkb = 2 * qb + 2;

    for (int kb = 0; kb < nkb; kb++) {
        __syncthreads();
#pragma unroll
        for (int i = 0; i < 4; i++) {
            const int idx = tid + 256 * i;
            const int r = idx >> 4, c = idx & 15;
            const float* kp = qkv + (bL + kb * 64 + r) * D3 + DMODEL + h * HDIM + c * 4;
            const float4 k4 = *(const float4*)kp;
            float* kd = Ks + r * AT_STRIDE + c * 4;
            kd[0] = tf32r(k4.x); kd[1] = tf32r(k4.y);
            kd[2] = tf32r(k4.z); kd[3] = tf32r(k4.w);
            const float4 v4 = *(const float4*)(kp + DMODEL);
            Vt[(c * 4 + 0) * AT_STRIDE + r] = tf32r(v4.x);
            Vt[(c * 4 + 1) * AT_STRIDE + r] = tf32r(v4.y);
            Vt[(c * 4 + 2) * AT_STRIDE + r] = tf32r(v4.z);
            Vt[(c * 4 + 3) * AT_STRIDE + r] = tf32r(v4.w);
        }
        __syncthreads();

        float sc[8][4];
#pragma unroll
        for (int n = 0; n < 8; n++)
#pragma unroll
            for (int q = 0; q < 4; q++) sc[n][q] = 0.f;
#pragma unroll
        for (int s = 0; s < 8; s++) {
            uint32_t bf[8][2];
#pragma unroll
            for (int p = 0; p < 4; p++) {
                uint32_t r4[4];
                ldsm4(r4, uKs + boff[p] + s * 32);
                bf[2 * p][0] = r4[0]; bf[2 * p][1] = r4[1];
                bf[2 * p + 1][0] = r4[2]; bf[2 * p + 1][1] = r4[3];
            }
#pragma unroll
            for (int n = 0; n < 8; n++) mma8(sc[n], qf[s], bf[n]);
        }

        const bool need_mask = (kb >= 2 * qb);
        const int c0g = kb * 64 + (lane & 3) * 2;
#pragma unroll
        for (int n = 0; n < 8; n++) {
            const int col0 = c0g + n * 8, col1 = col0 + 1;
            float s0 = sc[n][0] * 0.125f, s1 = sc[n][1] * 0.125f;
            float s2 = sc[n][2] * 0.125f, s3 = sc[n][3] * 0.125f;
            if (need_mask) {
                if (col0 > grow_lo) s0 = -1e30f;
                if (col1 > grow_lo) s1 = -1e30f;
                if (col0 > grow_hi) s2 = -1e30f;
                if (col1 > grow_hi) s3 = -1e30f;
            }
            sc[n][0] = s0; sc[n][1] = s1; sc[n][2] = s2; sc[n][3] = s3;
        }

        float bm_lo = -1e30f, bm_hi = -1e30f;
#pragma unroll
        for (int n = 0; n < 8; n++) {
            bm_lo = fmaxf(bm_lo, fmaxf(sc[n][0], sc[n][1]));
            bm_hi = fmaxf(bm_hi, fmaxf(sc[n][2], sc[n][3]));
        }
        bm_lo = fmaxf(bm_lo, __shfl_xor_sync(0xffffffffu, bm_lo, 1));
        bm_lo = fmaxf(bm_lo, __shfl_xor_sync(0xffffffffu, bm_lo, 2));
        bm_hi = fmaxf(bm_hi, __shfl_xor_sync(0xffffffffu, bm_hi, 1));
        bm_hi = fmaxf(bm_hi, __shfl_xor_sync(0xffffffffu, bm_hi, 2));
        const float mn_lo = fmaxf(m_lo, bm_lo);
        const float mn_hi = fmaxf(m_hi, bm_hi);
        const float f_lo = __expf(m_lo - mn_lo);
        const float f_hi = __expf(m_hi - mn_hi);
        m_lo = mn_lo; m_hi = mn_hi;

        float ps_lo = 0.f, ps_hi = 0.f;
#pragma unroll
        for (int n = 0; n < 8; n++) {
            sc[n][0] = __expf(sc[n][0] - mn_lo);
            sc[n][1] = __expf(sc[n][1] - mn_lo);
            sc[n][2] = __expf(sc[n][2] - mn_hi);
            sc[n][3] = __expf(sc[n][3] - mn_hi);
            ps_lo += sc[n][0] + sc[n][1];
            ps_hi += sc[n][2] + sc[n][3];
        }
        ps_lo += __shfl_xor_sync(0xffffffffu, ps_lo, 1);
        ps_lo += __shfl_xor_sync(0xffffffffu, ps_lo, 2);
        ps_hi += __shfl_xor_sync(0xffffffffu, ps_hi, 1);
        ps_hi += __shfl_xor_sync(0xffffffffu, ps_hi, 2);
        l_lo = l_lo * f_lo + ps_lo;
        l_hi = l_hi * f_hi + ps_hi;

#pragma unroll
        for (int n = 0; n < 8; n++) {
            oa[n][0] *= f_lo; oa[n][1] *= f_lo;
            oa[n][2] *= f_hi; oa[n][3] *= f_hi;
        }

        {
            float* prow_lo = Qs + (w * 16 + (lane >> 2)) * AT_STRIDE + (lane & 3) * 2;
            float* prow_hi = prow_lo + 8 * AT_STRIDE;
#pragma unroll
            for (int n = 0; n < 8; n++) {
                float2 p0; p0.x = tf32r(sc[n][0]); p0.y = tf32r(sc[n][1]);
                float2 p1; p1.x = tf32r(sc[n][2]); p1.y = tf32r(sc[n][3]);
                *(float2*)(prow_lo + n * 8) = p0;
                *(float2*)(prow_hi + n * 8) = p1;
            }
        }
        __syncwarp();

#pragma unroll
        for (int s = 0; s < 8; s++) {
            uint32_t ap[4];
            ldsm4(ap, uQs + aoff + s * 32);
#pragma unroll
            for (int p = 0; p < 4; p++) {
                uint32_t r4[4];
                ldsm4(r4, uVt + boff[p] + s * 32);
                uint32_t b0[2] = { r4[0], r4[1] };
                uint32_t b1[2] = { r4[2], r4[3] };
                mma8(oa[2 * p], ap, b0);
                mma8(oa[2 * p + 1], ap, b1);
            }
        }
    }

    const float inv_lo = 1.f / l_lo, inv_hi = 1.f / l_hi;
    __half* orow_lo = o + (bL + grow_lo) * DMODEL + h * HDIM + (lane & 3) * 2;
    __half* orow_hi = o + (bL + grow_hi) * DMODEL + h * HDIM + (lane & 3) * 2;
#pragma unroll
    for (int n = 0; n < 8; n++) {
        *(__half2*)(orow_lo + n * 8) = __floats2half2_rn(oa[n][0] * inv_lo, oa[n][1] * inv_lo);
        *(__half2*)(orow_hi + n * 8) = __floats2half2_rn(oa[n][2] * inv_hi, oa[n][3] * inv_hi);
    }
}

// ---------------- launcher ----------------
extern "C" void kernel_launch(void* const* d_in, const int* in_sizes, int n_in,
                              void* d_out, int out_size)
{
    const float* x     = (const float*)d_in[0];
    const float* w_qkv = (const float*)d_in[1];
    const float* b_qkv = (const float*)d_in[2];
    const float* w_out = (const float*)d_in[3];
    const float* b_out = (const float*)d_in[4];
    const float* w_fc1 = (const float*)d_in[5];
    const float* b_fc1 = (const float*)d_in[6];
    const float* w_fc2 = (const float*)d_in[7];
    const float* b_fc2 = (const float*)d_in[8];
    const float* ln1_g = (const float*)d_in[9];
    const float* ln1_b = (const float*)d_in[10];
    const float* ln2_g = (const float*)d_in[11];
    const float* ln2_b = (const float*)d_in[12];
    float* out = (float*)d_out;

    __half *h, *o, *fc1, *wT;
    float *qkv, *x1;
    cudaGetSymbolAddress((void**)&h,   g_hh);
    cudaGetSymbolAddress((void**)&qkv, g_qkv);
    cudaGetSymbolAddress((void**)&o,   g_oh);
    cudaGetSymbolAddress((void**)&x1,  g_x1);
    cudaGetSymbolAddress((void**)&fc1, g_fc1h);
    cudaGetSymbolAddress((void**)&wT,  g_wTh);

    __half* wqkvT = wT;                       // [3072,1024]
    __half* woutT = wqkvT + 3072 * 1024;      // [1024,1024]
    __half* wfc1T = woutT + 1024 * 1024;      // [4096,1024]
    __half* wfc2T = wfc1T + 4096 * 1024;      // [1024,4096]

    cudaFuncSetAttribute((const void*)hgemm_tc<0, float>,  cudaFuncAttributeMaxDynamicSharedMemorySize, GEMM_SMEM);
    cudaFuncSetAttribute((const void*)hgemm_tc<1, float>,  cudaFuncAttributeMaxDynamicSharedMemorySize, GEMM_SMEM);
    cudaFuncSetAttribute((const void*)hgemm_tc<2, __half>, cudaFuncAttributeMaxDynamicSharedMemorySize, GEMM_SMEM);
    cudaFuncSetAttribute(attn_tc_kernel, cudaFuncAttributeMaxDynamicSharedMemorySize, ATT_SMEM);

    // 0) transpose weights (fp16)
    transpose_kernel<<<dim3(D3 / 32,    DMODEL / 32), 256>>>(w_qkv, wqkvT, DMODEL, D3);
    transpose_kernel<<<dim3(DMODEL / 32, DMODEL / 32), 256>>>(w_out, woutT, DMODEL, DMODEL);
    transpose_kernel<<<dim3(INNER / 32,  DMODEL / 32), 256>>>(w_fc1, wfc1T, DMODEL, INNER);
    transpose_kernel<<<dim3(DMODEL / 32, INNER / 32), 256>>>(w_fc2, wfc2T, INNER, DMODEL);

    // 1) LN1 (fp16 out)
    ln_kernel<<<MROWS, 256>>>(x, ln1_g, ln1_b, h);

    // 2) QKV projection (fp16 in, fp32 out)
    hgemm_tc<0, float><<<dim3(D3 / 128, MROWS / 128), 256, GEMM_SMEM>>>(
        h, wqkvT, b_qkv, nullptr, qkv, MROWS, D3, DMODEL);

    // 3) causal attention (tf32 tensor cores, fp16 out)
    attn_tc_kernel<<<dim3(SEQ / 128, BATCH * NHEAD), 256, ATT_SMEM>>>(qkv, o);

    // 4) out projection + residual (fp32 out)
    hgemm_tc<1, float><<<dim3(DMODEL / 128, MROWS / 128), 256, GEMM_SMEM>>>(
        o, woutT, b_out, x, x1, MROWS, DMODEL, DMODEL);

    // 5) LN2 (fp16 out)
    ln_kernel<<<MROWS, 256>>>(x1, ln2_g, ln2_b, h);

    // 6) FC1 + exact GELU (fp16 out)
    hgemm_tc<2, __half><<<dim3(INNER / 128, MROWS / 128), 256, GEMM_SMEM>>>(
        h, wfc1T, b_fc1, nullptr, fc1, MROWS, INNER, DMODEL);

    // 7) FC2 + residual -> out (fp32)
    hgemm_tc<1, float><<<dim3(DMODEL / 128, MROWS / 128), 256, GEMM_SMEM>>>(
        fc1, wfc2T, b_fc2, x1, out, MROWS, DMODEL, INNER);
}

// round 7
// speedup vs baseline: 7.9213x; 1.1352x over previous
#include <cuda_runtime.h>
#include <cuda_fp16.h>
#include <cuda_bf16.h>
#include <math.h>
#include <cstdint>

// Problem constants
#define BATCH 2
#define SEQ   2048
#define MROWS (BATCH*SEQ)       // 4096
#define DMODEL 1024
#define D3    (3*DMODEL)        // 3072
#define INNER (4*DMODEL)        // 4096
#define NHEAD 16
#define HDIM  64

// ---------------- scratch (device globals; no allocations allowed) ----------
__device__ __half g_hh  [MROWS*DMODEL];   // LN output (fp16)
__device__ __half g_qkvh[MROWS*D3];       // QKV projection (fp16)
__device__ __half g_oh  [MROWS*DMODEL];   // attention output (fp16)
__device__ float  g_x1  [MROWS*DMODEL];   // residual after attention (fp32)
__device__ __half g_fc1h[MROWS*INNER];    // FC1+GELU output (fp16)
__device__ __half g_wTh [12*1024*1024];   // transposed fp16 weights

// ---------------- helpers ----------------
__device__ __forceinline__ uint32_t smem_u32(const void* p) {
    uint32_t a;
    asm("{ .reg .u64 t; cvta.to.shared.u64 t, %1; cvt.u32.u64 %0, t; }" : "=r"(a) : "l"(p));
    return a;
}
#define SW64(x)  ((x) ^ (((x) >> 3) & 0x30))
#define SW128(x) ((x) ^ (((x) >> 3) & 0x70))
#define CP16(sa, ga) \
    asm volatile("cp.async.cg.shared.global [%0], [%1], 16;" :: "r"(sa), "l"(ga) : "memory")

__device__ __forceinline__ void ldsm4(uint32_t* r, uint32_t a) {
    asm volatile("ldmatrix.sync.aligned.m8n8.x4.shared.b16 {%0,%1,%2,%3}, [%4];"
        : "=r"(r[0]), "=r"(r[1]), "=r"(r[2]), "=r"(r[3]) : "r"(a));
}
__device__ __forceinline__ void ldsm4t(uint32_t* r, uint32_t a) {
    asm volatile("ldmatrix.sync.aligned.m8n8.x4.trans.shared.b16 {%0,%1,%2,%3}, [%4];"
        : "=r"(r[0]), "=r"(r[1]), "=r"(r[2]), "=r"(r[3]) : "r"(a));
}
// fp16 MMA: D(16x8,f32) += A(16x16,f16) * B(8x16,f16)^T
__device__ __forceinline__ void mma16(float* d, const uint32_t* a, const uint32_t* b) {
    asm volatile("mma.sync.aligned.m16n8k16.row.col.f32.f16.f16.f32 "
        "{%0,%1,%2,%3}, {%4,%5,%6,%7}, {%8,%9}, {%0,%1,%2,%3};"
        : "+f"(d[0]), "+f"(d[1]), "+f"(d[2]), "+f"(d[3])
        : "r"(a[0]), "r"(a[1]), "r"(a[2]), "r"(a[3]), "r"(b[0]), "r"(b[1]));
}

// ---------------- transpose to fp16: dst[C,R] = half(src[R,C]^T) ------------
__global__ __launch_bounds__(256) void transpose_kernel(
    const float* __restrict__ src, __half* __restrict__ dst, int R, int C)
{
    __shared__ float tile[32][33];
    const int c0 = blockIdx.x * 32, r0 = blockIdx.y * 32;
    const int tx = threadIdx.x & 31, ty = threadIdx.x >> 5;
#pragma unroll
    for (int i = 0; i < 4; i++)
        tile[ty + 8 * i][tx] = src[(size_t)(r0 + ty + 8 * i) * C + c0 + tx];
    __syncthreads();
#pragma unroll
    for (int i = 0; i < 4; i++)
        dst[(size_t)(c0 + ty + 8 * i) * R + r0 + tx] = __float2half(tile[tx][ty + 8 * i]);
}

// ---------------- fp16 tensor-core GEMM: C = A[M,K] @ Bt[N,K]^T + bias ------
#define GS_ABYTES 8192
#define GS_STAGE  16384
#define GEMM_SMEM (4 * GS_STAGE)   // 65536

template<int EPI, typename CT>
__global__ __launch_bounds__(256) void hgemm_tc(
    const __half* __restrict__ A, const __half* __restrict__ Bt,
    const float* __restrict__ bias, const float* __restrict__ res,
    CT* __restrict__ C, int M, int N, int K)
{
    extern __shared__ char smem[];
    const uint32_t sb = smem_u32(smem);
    const int tid = threadIdx.x, lane = tid & 31, wid = tid >> 5;
    const int warp_m = wid >> 2, warp_n = wid & 3;
    const int m0 = blockIdx.y * 128, n0 = blockIdx.x * 128;
    const int mb = warp_m * 64, nb = warp_n * 32;

    const int cr = (wid * 8) + (lane & 7);
    const int cc = lane >> 3;

    const int u = lane >> 3, ur = lane & 7;
    uint32_t aoff[4], boff[2];
#pragma unroll
    for (int i = 0; i < 4; i++)
        aoff[i] = (uint32_t)(mb + i * 16 + (u & 1) * 8 + ur) * 64 + (u >> 1) * 16;
#pragma unroll
    for (int p = 0; p < 2; p++)
        boff[p] = (uint32_t)(nb + p * 16 + (u >> 1) * 8 + ur) * 64 + (u & 1) * 16;

    float acc[4][4][4];
#pragma unroll
    for (int i = 0; i < 4; i++)
#pragma unroll
        for (int j = 0; j < 4; j++)
#pragma unroll
            for (int q = 0; q < 4; q++) acc[i][j][q] = 0.f;

    const int nk = K >> 5;

#define H_ISSUE(t)                                                             \
    do {                                                                       \
        const uint32_t sa_ = sb + ((t) & 3) * GS_STAGE;                        \
        const uint32_t sbB_ = sa_ + GS_ABYTES;                                 \
        _Pragma("unroll")                                                      \
        for (int p_ = 0; p_ < 2; p_++) {                                       \
            const int r_ = cr + 64 * p_;                                       \
            const uint32_t so_ = SW64((uint32_t)r_ * 64 + cc * 16);            \
            CP16(sa_ + so_, A + (size_t)(m0 + r_) * K + (t) * 32 + cc * 8);    \
            CP16(sbB_ + so_, Bt + (size_t)(n0 + r_) * K + (t) * 32 + cc * 8);  \
        }                                                                      \
        asm volatile("cp.async.commit_group;" ::: "memory");                   \
    } while (0)

    H_ISSUE(0); H_ISSUE(1); H_ISSUE(2);

    for (int t = 0; t < nk; t++) {
        const int rem = nk - 1 - t;
        if (rem >= 2)       asm volatile("cp.async.wait_group 2;" ::: "memory");
        else if (rem == 1)  asm volatile("cp.async.wait_group 1;" ::: "memory");
        else                asm volatile("cp.async.wait_group 0;" ::: "memory");
        __syncthreads();

        if (t + 3 < nk) H_ISSUE(t + 3);

        const uint32_t sa = sb + (t & 3) * GS_STAGE;
        const uint32_t sbB = sa + GS_ABYTES;
#pragma unroll
        for (int s = 0; s < 2; s++) {
            uint32_t af[4][4], bf[4][2];
#pragma unroll
            for (int i = 0; i < 4; i++)
                ldsm4(af[i], sa + SW64(aoff[i] + s * 32));
#pragma unroll
            for (int p = 0; p < 2; p++) {
                uint32_t r4[4];
                ldsm4(r4, sbB + SW64(boff[p] + s * 32));
                bf[2 * p][0] = r4[0]; bf[2 * p][1] = r4[1];
                bf[2 * p + 1][0] = r4[2]; bf[2 * p + 1][1] = r4[3];
            }
#pragma unroll
            for (int i = 0; i < 4; i++)
#pragma unroll
                for (int j = 0; j < 4; j++) mma16(acc[i][j], af[i], bf[j]);
        }
        __syncthreads();
    }
#undef H_ISSUE

    const int r0 = m0 + mb + (lane >> 2);
    const int c0 = n0 + nb + (lane & 3) * 2;
#pragma unroll
    for (int i = 0; i < 4; i++) {
#pragma unroll
        for (int j = 0; j < 4; j++) {
            const int col = c0 + j * 8;
            const float bx = bias[col], by = bias[col + 1];
#pragma unroll
            for (int hh = 0; hh < 2; hh++) {
                const int row = r0 + i * 16 + hh * 8;
                float vx = acc[i][j][hh * 2 + 0] + bx;
                float vy = acc[i][j][hh * 2 + 1] + by;
                if (EPI == 1) {
                    const float2 rr = *(const float2*)(res + (size_t)row * N + col);
                    vx += rr.x; vy += rr.y;
                }
                if (EPI == 2) {
                    vx = 0.5f * vx * (1.f + erff(vx * 0.70710678118654752f));
                    vy = 0.5f * vy * (1.f + erff(vy * 0.70710678118654752f));
                }
                CT* cp = C + (size_t)row * N + col;
                if (sizeof(CT) == 2) {
                    *(__half2*)cp = __floats2half2_rn(vx, vy);
                } else {
                    float2 v; v.x = vx; v.y = vy;
                    *(float2*)cp = v;
                }
            }
        }
    }
}

// ---------------- LayerNorm (fp16 output) -----------------------------------
__global__ __launch_bounds__(256) void ln_kernel(
    const float* __restrict__ x, const float* __restrict__ g,
    const float* __restrict__ b, __half* __restrict__ out)
{
    __shared__ float red[16];
    const long row = blockIdx.x;
    const float* xr = x + row * DMODEL;
    const int tid = threadIdx.x;

    float v[4];
    float s1 = 0.f, s2 = 0.f;
#pragma unroll
    for (int i = 0; i < 4; i++) {
        v[i] = xr[tid + 256 * i];
        s1 += v[i];
        s2 += v[i] * v[i];
    }
#pragma unroll
    for (int o = 16; o; o >>= 1) {
        s1 += __shfl_xor_sync(0xffffffffu, s1, o);
        s2 += __shfl_xor_sync(0xffffffffu, s2, o);
    }
    if ((tid & 31) == 0) { red[tid >> 5] = s1; red[8 + (tid >> 5)] = s2; }
    __syncthreads();
    if (tid < 32) {
        float a = (tid < 8) ? red[tid] : 0.f;
        float c = (tid < 8) ? red[8 + tid] : 0.f;
#pragma unroll
        for (int o = 4; o; o >>= 1) {
            a += __shfl_xor_sync(0xffffffffu, a, o);
            c += __shfl_xor_sync(0xffffffffu, c, o);
        }
        if (tid == 0) { red[0] = a; red[8] = c; }
    }
    __syncthreads();
    const float mu  = red[0] * (1.f / DMODEL);
    const float var = red[8] * (1.f / DMODEL) - mu * mu;
    const float r   = rsqrtf(var + 1e-5f);
#pragma unroll
    for (int i = 0; i < 4; i++) {
        const int c = tid + 256 * i;
        out[row * DMODEL + c] = __float2half((v[i] - mu) * r * g[c] + b[c]);
    }
}

// ---------------- fp16 tensor-core flash attention --------------------------
// Per CTA: one (b,h), 128 query rows, 8 warps x 16 rows. K-blocks of 64.
// Smem (128B rows, SW128): Q/P [128][64]h = 16KB, K [64][64]h = 8KB, V = 8KB.
#define ATT_SMEM (16384 + 8192 + 8192)

__global__ __launch_bounds__(256) void attn_h_kernel(
    const __half* __restrict__ qkv, __half* __restrict__ o)
{
    extern __shared__ char sm[];
    const uint32_t uQ = smem_u32(sm);
    const uint32_t uK = uQ + 16384;
    const uint32_t uV = uK + 8192;

    const int tid = threadIdx.x, lane = tid & 31, w = tid >> 5;
    const int bh = blockIdx.y;
    const int b = bh >> 4, h = bh & 15;
    const int qb = (int)gridDim.x - 1 - (int)blockIdx.x;   // heavy tiles first
    const int q0 = qb * 128;
    const size_t bL = (size_t)b * SEQ;

    const int u = lane >> 3, ur = lane & 7;
    // A-fragment offsets (Q and P): rows of 128B
    const uint32_t aoff = (uint32_t)(w * 16 + (u & 1) * 8 + ur) * 128 + (u >> 1) * 16;
    // B-fragment offsets for K (non-trans): n = key rows
    uint32_t boffK[4];
#pragma unroll
    for (int p = 0; p < 4; p++)
        boffK[p] = (uint32_t)(p * 16 + (u >> 1) * 8 + ur) * 128 + (u & 1) * 16;
    // B-fragment offsets for V (trans): rows = keys, cols = hd
    uint32_t boffV[4];
#pragma unroll
    for (int p = 0; p < 4; p++)
        boffV[p] = (uint32_t)((u & 1) * 8 + ur) * 128 + p * 32 + (u >> 1) * 16;

    // ---- load Q tile (128 rows x 128B) ----
#pragma unroll
    for (int i = 0; i < 4; i++) {
        const int idx = tid + 256 * i;
        const int r = idx >> 3, c = idx & 7;
        CP16(uQ + SW128((uint32_t)r * 128 + c * 16),
             qkv + (bL + q0 + r) * D3 + h * HDIM + c * 8);
    }
    asm volatile("cp.async.commit_group;" ::: "memory");
    asm volatile("cp.async.wait_group 0;" ::: "memory");
    __syncthreads();

    // ---- Q fragments to registers (4 k16 steps x 4 regs) ----
    uint32_t qf[4][4];
#pragma unroll
    for (int s = 0; s < 4; s++) ldsm4(qf[s], uQ + SW128(aoff + s * 32));

    float oa[8][4];
#pragma unroll
    for (int n = 0; n < 8; n++)
#pragma unroll
        for (int q = 0; q < 4; q++) oa[n][q] = 0.f;
    float m_lo = -1e30f, m_hi = -1e30f, l_lo = 0.f, l_hi = 0.f;

    const int grow_lo = q0 + w * 16 + (lane >> 2);
    const int grow_hi = grow_lo + 8;
    const int nkb = 2 * qb + 2;

    for (int kb = 0; kb < nkb; kb++) {
        __syncthreads();
        // ---- load K and V tiles (64 rows x 128B each) ----
#pragma unroll
        for (int i = 0; i < 2; i++) {
            const int idx = tid + 256 * i;
            const int r = idx >> 3, c = idx & 7;
            const uint32_t so = SW128((uint32_t)r * 128 + c * 16);
            const __half* kp = qkv + (bL + kb * 64 + r) * D3 + DMODEL + h * HDIM + c * 8;
            CP16(uK + so, kp);
            CP16(uV + so, kp + DMODEL);
        }
        asm volatile("cp.async.commit_group;" ::: "memory");
        asm volatile("cp.async.wait_group 0;" ::: "memory");
        __syncthreads();

        // ---- S = Q @ K^T (32 mma16) ----
        float sc[8][4];
#pragma unroll
        for (int n = 0; n < 8; n++)
#pragma unroll
            for (int q = 0; q < 4; q++) sc[n][q] = 0.f;
#pragma unroll
        for (int s = 0; s < 4; s++) {
            uint32_t bf[8][2];
#pragma unroll
            for (int p = 0; p < 4; p++) {
                uint32_t r4[4];
                ldsm4(r4, uK + SW128(boffK[p] + s * 32));
                bf[2 * p][0] = r4[0]; bf[2 * p][1] = r4[1];
                bf[2 * p + 1][0] = r4[2]; bf[2 * p + 1][1] = r4[3];
            }
#pragma unroll
            for (int n = 0; n < 8; n++) mma16(sc[n], qf[s], bf[n]);
        }

        // ---- scale + causal mask ----
        const bool need_mask = (kb >= 2 * qb);
        const int c0g = kb * 64 + (lane & 3) * 2;
#pragma unroll
        for (int n = 0; n < 8; n++) {
            const int col0 = c0g + n * 8, col1 = col0 + 1;
            float s0 = sc[n][0] * 0.125f, s1 = sc[n][1] * 0.125f;
            float s2 = sc[n][2] * 0.125f, s3 = sc[n][3] * 0.125f;
            if (need_mask) {
                if (col0 > grow_lo) s0 = -1e30f;
                if (col1 > grow_lo) s1 = -1e30f;
                if (col0 > grow_hi) s2 = -1e30f;
                if (col1 > grow_hi) s3 = -1e30f;
            }
            sc[n][0] = s0; sc[n][1] = s1; sc[n][2] = s2; sc[n][3] = s3;
        }

        // ---- online softmax ----
        float bm_lo = -1e30f, bm_hi = -1e30f;
#pragma unroll
        for (int n = 0; n < 8; n++) {
            bm_lo = fmaxf(bm_lo, fmaxf(sc[n][0], sc[n][1]));
            bm_hi = fmaxf(bm_hi, fmaxf(sc[n][2], sc[n][3]));
        }
        bm_lo = fmaxf(bm_lo, __shfl_xor_sync(0xffffffffu, bm_lo, 1));
        bm_lo = fmaxf(bm_lo, __shfl_xor_sync(0xffffffffu, bm_lo, 2));
        bm_hi = fmaxf(bm_hi, __shfl_xor_sync(0xffffffffu, bm_hi, 1));
        bm_hi = fmaxf(bm_hi, __shfl_xor_sync(0xffffffffu, bm_hi, 2));
        const float mn_lo = fmaxf(m_lo, bm_lo);
        const float mn_hi = fmaxf(m_hi, bm_hi);
        const float f_lo = __expf(m_lo - mn_lo);
        const float f_hi = __expf(m_hi - mn_hi);
        m_lo = mn_lo; m_hi = mn_hi;

        float ps_lo = 0.f, ps_hi = 0.f;
#pragma unroll
        for (int n = 0; n < 8; n++) {
            sc[n][0] = __expf(sc[n][0] - mn_lo);
            sc[n][1] = __expf(sc[n][1] - mn_lo);
            sc[n][2] = __expf(sc[n][2] - mn_hi);
            sc[n][3] = __expf(sc[n][3] - mn_hi);
            ps_lo += sc[n][0] + sc[n][1];
            ps_hi += sc[n][2] + sc[n][3];
        }
        ps_lo += __shfl_xor_sync(0xffffffffu, ps_lo, 1);
        ps_lo += __shfl_xor_sync(0xffffffffu, ps_lo, 2);
        ps_hi += __shfl_xor_sync(0xffffffffu, ps_hi, 1);
        ps_hi += __shfl_xor_sync(0xffffffffu, ps_hi, 2);
        l_lo = l_lo * f_lo + ps_lo;
        l_hi = l_hi * f_hi + ps_hi;

#pragma unroll
        for (int n = 0; n < 8; n++) {
            oa[n][0] *= f_lo; oa[n][1] *= f_lo;
            oa[n][2] *= f_hi; oa[n][3] *= f_hi;
        }

        // ---- write P to smem (fp16, warp-private rows in Q region) ----
        {
            const uint32_t plo = (uint32_t)(w * 16 + (lane >> 2)) * 128 + (lane & 3) * 4;
            const uint32_t phi = plo + 8 * 128;
#pragma unroll
            for (int n = 0; n < 8; n++) {
                *(__half2*)(sm + SW128(plo + n * 16)) = __floats2half2_rn(sc[n][0], sc[n][1]);
                *(__half2*)(sm + SW128(phi + n * 16)) = __floats2half2_rn(sc[n][2], sc[n][3]);
            }
        }
        __syncwarp();

        // ---- O += P @ V (32 mma16, V via ldmatrix.trans) ----
#pragma unroll
        for (int s = 0; s < 4; s++) {
            uint32_t ap[4];
            ldsm4(ap, uQ + SW128(aoff + s * 32));
#pragma unroll
            for (int p = 0; p < 4; p++) {
                uint32_t r4[4];
                ldsm4t(r4, uV + SW128(boffV[p] + s * 16 * 128));
                uint32_t b0[2] = { r4[0], r4[1] };
                uint32_t b1[2] = { r4[2], r4[3] };
                mma16(oa[2 * p], ap, b0);
                mma16(oa[2 * p + 1], ap, b1);
            }
        }
    }

    // ---- epilogue ----
    const float inv_lo = 1.f / l_lo, inv_hi = 1.f / l_hi;
    __half* orow_lo = o + (bL + grow_lo) * DMODEL + h * HDIM + (lane & 3) * 2;
    __half* orow_hi = o + (bL + grow_hi) * DMODEL + h * HDIM + (lane & 3) * 2;
#pragma unroll
    for (int n = 0; n < 8; n++) {
        *(__half2*)(orow_lo + n * 8) = __floats2half2_rn(oa[n][0] * inv_lo, oa[n][1] * inv_lo);
        *(__half2*)(orow_hi + n * 8) = __floats2half2_rn(oa[n][2] * inv_hi, oa[n][3] * inv_hi);
    }
}

// ---------------- launcher ----------------
extern "C" void kernel_launch(void* const* d_in, const int* in_sizes, int n_in,
                              void* d_out, int out_size)
{
    const float* x     = (const float*)d_in[0];
    const float* w_qkv = (const float*)d_in[1];
    const float* b_qkv = (const float*)d_in[2];
    const float* w_out = (const float*)d_in[3];
    const float* b_out = (const float*)d_in[4];
    const float* w_fc1 = (const float*)d_in[5];
    const float* b_fc1 = (const float*)d_in[6];
    const float* w_fc2 = (const float*)d_in[7];
    const float* b_fc2 = (const float*)d_in[8];
    const float* ln1_g = (const float*)d_in[9];
    const float* ln1_b = (const float*)d_in[10];
    const float* ln2_g = (const float*)d_in[11];
    const float* ln2_b = (const float*)d_in[12];
    float* out = (float*)d_out;

    __half *h, *qkv, *o, *fc1, *wT;
    float *x1;
    cudaGetSymbolAddress((void**)&h,   g_hh);
    cudaGetSymbolAddress((void**)&qkv, g_qkvh);
    cudaGetSymbolAddress((void**)&o,   g_oh);
    cudaGetSymbolAddress((void**)&x1,  g_x1);
    cudaGetSymbolAddress((void**)&fc1, g_fc1h);
    cudaGetSymbolAddress((void**)&wT,  g_wTh);

    __half* wqkvT = wT;                       // [3072,1024]
    __half* woutT = wqkvT + 3072 * 1024;      // [1024,1024]
    __half* wfc1T = woutT + 1024 * 1024;      // [4096,1024]
    __half* wfc2T = wfc1T + 4096 * 1024;      // [1024,4096]

    cudaFuncSetAttribute((const void*)hgemm_tc<0, __half>, cudaFuncAttributeMaxDynamicSharedMemorySize, GEMM_SMEM);
    cudaFuncSetAttribute((const void*)hgemm_tc<1, float>,  cudaFuncAttributeMaxDynamicSharedMemorySize, GEMM_SMEM);
    cudaFuncSetAttribute((const void*)hgemm_tc<2, __half>, cudaFuncAttributeMaxDynamicSharedMemorySize, GEMM_SMEM);
    cudaFuncSetAttribute(attn_h_kernel, cudaFuncAttributeMaxDynamicSharedMemorySize, ATT_SMEM);

    // 0) transpose weights (fp16)
    transpose_kernel<<<dim3(D3 / 32,    DMODEL / 32), 256>>>(w_qkv, wqkvT, DMODEL, D3);
    transpose_kernel<<<dim3(DMODEL / 32, DMODEL / 32), 256>>>(w_out, woutT, DMODEL, DMODEL);
    transpose_kernel<<<dim3(INNER / 32,  DMODEL / 32), 256>>>(w_fc1, wfc1T, DMODEL, INNER);
    transpose_kernel<<<dim3(DMODEL / 32, INNER / 32), 256>>>(w_fc2, wfc2T, INNER, DMODEL);

    // 1) LN1 (fp16 out)
    ln_kernel<<<MROWS, 256>>>(x, ln1_g, ln1_b, h);

    // 2) QKV projection (fp16 out)
    hgemm_tc<0, __half><<<dim3(D3 / 128, MROWS / 128), 256, GEMM_SMEM>>>(
        h, wqkvT, b_qkv, nullptr, qkv, MROWS, D3, DMODEL);

    // 3) causal attention (fp16 tensor cores)
    attn_h_kernel<<<dim3(SEQ / 128, BATCH * NHEAD), 256, ATT_SMEM>>>(qkv, o);

    // 4) out projection + residual (fp32 out)
    hgemm_tc<1, float><<<dim3(DMODEL / 128, MROWS / 128), 256, GEMM_SMEM>>>(
        o, woutT, b_out, x, x1, MROWS, DMODEL, DMODEL);

    // 5) LN2 (fp16 out)
    ln_kernel<<<MROWS, 256>>>(x1, ln2_g, ln2_b, h);

    // 6) FC1 + exact GELU (fp16 out)
    hgemm_tc<2, __half><<<dim3(INNER / 128, MROWS / 128), 256, GEMM_SMEM>>>(
        h, wfc1T, b_fc1, nullptr, fc1, MROWS, INNER, DMODEL);

    // 7) FC2 + residual -> out (fp32)
    hgemm_tc<1, float><<<dim3(DMODEL / 128, MROWS / 128), 256, GEMM_SMEM>>>(
        fc1, wfc2T, b_fc2, x1, out, MROWS, DMODEL, INNER);
}